// round 13
// baseline (speedup 1.0000x reference)
#include <cuda_runtime.h>
#include <cuda_bf16.h>
#include <mma.h>
#include <cstdint>

using namespace nvcuda;

#define LSEQ 4608
#define CDIM 640
#define DI   1280
#define DXZ  2560
#define NPROJ 56
#define RANK  40
#define PLANE 2304          // 48*48
#define XFSZ  (640*2304)
#define PSLICE (LSEQ*NPROJ)
#define NCHUNK 72
#define CLEN   64
#define DS     (DI*8)
#define KSPLIT 16

// ---------------- scratch ----------------
__device__ float g_xz  [LSEQ*DXZ];
__device__ float g_xa  [LSEQ*DI];
__device__ float g_proj[LSEQ*NPROJ];
__device__ float g_pp  [KSPLIT*PSLICE];
__device__ float g_dt  [LSEQ*DI];
__device__ float g_cP  [NCHUNK*DS];
__device__ float g_cH  [NCHUNK*DS];
__device__ float g_h0  [NCHUNK*DS];
// bf16 operands: activations get hi/lo split; weights hi only (2-term scheme)
__device__ __align__(256) __nv_bfloat16 g_a1hi[LSEQ*CDIM], g_a1lo[LSEQ*CDIM]; // ln(seq)
__device__ __align__(256) __nv_bfloat16 g_b1hi[DXZ*CDIM];                     // W_in^T
__device__ __align__(256) __nv_bfloat16 g_a2hi[LSEQ*DI],   g_a2lo[LSEQ*DI];   // yo
__device__ __align__(256) __nv_bfloat16 g_b2hi[CDIM*DI];                      // W_out^T

// ---------------- helpers ----------------
#define CP_ASYNC16(dst, src) \
    asm volatile("cp.async.cg.shared.global [%0], [%1], 16;" :: "r"(dst), "l"(src) : "memory")
#define CP_COMMIT() asm volatile("cp.async.commit_group;" ::: "memory")
#define CP_WAIT(n)  asm volatile("cp.async.wait_group %0;" :: "n"(n) : "memory")

__device__ __forceinline__ uint32_t smem_u32(const void* p){
    uint32_t a;
    asm("{ .reg .u64 t; cvta.to.shared.u64 t, %1; cvt.u32.u64 %0, t; }" : "=r"(a) : "l"(p));
    return a;
}
__device__ __forceinline__ float silu_f(float v){ return v / (1.0f + __expf(-v)); }
__device__ __forceinline__ void split_store(float v, __nv_bfloat16* hi, __nv_bfloat16* lo, size_t off){
    __nv_bfloat16 h = __float2bfloat16(v);
    hi[off] = h;
    lo[off] = __float2bfloat16(v - __bfloat162float(h));
}

// ---------------- 1) gather + layernorm -> bf16 hi/lo (coalesced via smem transpose) ----
#define LN_SMEM ((16000 + 640 + 640) * 4)
__global__ void __launch_bounds__(256)
ln_kernel(const float* __restrict__ x, const float* __restrict__ yy,
          const float* __restrict__ g, const float* __restrict__ b){
    extern __shared__ float sm[];             // T[640*25] | gg[640] | bb[640]
    float* T  = sm;
    float* gg = sm + 16000;
    float* bb = sm + 16640;
    int bid = blockIdx.x;                     // 0..191
    bool isx = bid < 96;
    int hb = bid - (isx ? 0 : 96);
    int h  = hb >> 1;
    int w0 = (hb & 1) * 24;
    const float* src = (isx ? x : yy) + h*48 + w0;
    int tid = threadIdx.x;

    for (int e = tid; e < 640; e += 256){ gg[e] = g[e]; bb[e] = b[e]; }
    for (int e = tid; e < 15360; e += 256){
        int c = e / 24, w = e - c*24;
        T[c*25 + w] = src[(size_t)c * PLANE + w];
    }
    __syncthreads();

    int wid = tid >> 5, lane = tid & 31;
    #pragma unroll
    for (int pi = 0; pi < 3; pi++){
        int p = wid + pi*8;                   // 0..23
        float s = 0.f, s2 = 0.f;
        #pragma unroll
        for (int k = 0; k < 20; k++){
            float v = T[(lane + k*32)*25 + p];
            s += v; s2 += v*v;
        }
        #pragma unroll
        for (int o = 16; o; o >>= 1){
            s  += __shfl_xor_sync(0xffffffffu, s , o);
            s2 += __shfl_xor_sync(0xffffffffu, s2, o);
        }
        float mean = s  * (1.f/640.f);
        float var  = s2 * (1.f/640.f) - mean*mean;
        float inv  = rsqrtf(var + 1e-5f);
        int l = h*96 + (isx ? 0 : 48) + w0 + p;
        size_t base = (size_t)l * CDIM;
        #pragma unroll
        for (int k = 0; k < 20; k++){
            int c = lane + k*32;
            float o = (T[c*25 + p] - mean) * inv * gg[c] + bb[c];
            split_store(o, g_a1hi, g_a1lo, base + c);
        }
    }
}

// ---------------- weight transposes (both) + bf16 hi: W[K,N] -> Wt[n*K+k] ----------------
// blocks [0,1600): W_in (640x2560); blocks [1600,2400): W_out (1280x640)
__global__ void transpose_both(const float* __restrict__ Wi, const float* __restrict__ Wo,
                               __nv_bfloat16* __restrict__ b1h, __nv_bfloat16* __restrict__ b2h){
    __shared__ float tile[32][33];
    int id = blockIdx.x;
    const float* W; __nv_bfloat16* hi; int K, N, bx, by;
    if (id < 1600){ W = Wi; hi = b1h; K = CDIM; N = DXZ; bx = id % 80; by = id / 80; }
    else { int j = id - 1600; W = Wo; hi = b2h; K = DI; N = CDIM; bx = j % 20; by = j / 20; }
    int n0 = bx * 32, k0 = by * 32;
    int tx = threadIdx.x, ty = threadIdx.y;   // (32, 8)
    #pragma unroll
    for (int i = 0; i < 4; i++)
        tile[ty + 8*i][tx] = W[(size_t)(k0 + ty + 8*i) * N + n0 + tx];
    __syncthreads();
    #pragma unroll
    for (int i = 0; i < 4; i++){
        float v = tile[tx][ty + 8*i];
        hi[(size_t)(n0 + ty + 8*i) * K + k0 + tx] = __float2bfloat16(v);
    }
}

// ---------------- wmma 2-term bf16-split GEMM: C = (Ahi+Alo) @ Bhi^T ----------------
#define LDS_E 40                         // bf16 smem row stride (80B)

template<int MODE, int MW, int NTILE, int NSTAGE, int MAXB>
__global__ void __launch_bounds__(256, MAXB)
gemm_wmma(const __nv_bfloat16* __restrict__ Ahi, const __nv_bfloat16* __restrict__ Alo,
          const __nv_bfloat16* __restrict__ Bhi,
          float* __restrict__ C, int K, int Nc,
          const float* __restrict__ rx, const float* __restrict__ ry,
          float* __restrict__ outp){
    constexpr int MTILE = MW * 32;
    constexpr int NW    = 8 / MW;
    constexpr int WNT   = NTILE / NW;
    constexpr int NJ    = WNT / 16;
    constexpr int A_TB  = MTILE * LDS_E * 2;
    constexpr int B_TB  = NTILE * LDS_E * 2;
    constexpr int SS    = 2*A_TB + B_TB;
    constexpr int STGL  = WNT + 4;

    extern __shared__ __align__(32) char smem[];
    uint32_t sbase = smem_u32(smem);
    int tid = threadIdx.x;
    int wid = tid >> 5, lane = tid & 31;
    int wr = wid % MW, wc = wid / MW;
    int n0 = blockIdx.x * NTILE, m0 = blockIdx.y * MTILE;

    const char* asrc[2] = {
        (const char*)(Ahi + (size_t)m0 * K), (const char*)(Alo + (size_t)m0 * K) };
    const char* bsrc = (const char*)(Bhi + (size_t)n0 * K);
    int rowbytes = K * 2;
    int nstage = K / 32;

    wmma::fragment<wmma::accumulator, 16, 16, 16, float> acc[2][NJ];
    #pragma unroll
    for (int i = 0; i < 2; i++)
        #pragma unroll
        for (int j = 0; j < NJ; j++) wmma::fill_fragment(acc[i][j], 0.f);

    auto load_stage = [&](int st, int k0bytes){
        uint32_t sb = sbase + (uint32_t)(st * SS);
        #pragma unroll
        for (int tl = 0; tl < 2; tl++){
            const char* bp = asrc[tl] + k0bytes;
            uint32_t tb = sb + (uint32_t)(tl * A_TB);
            #pragma unroll
            for (int j = 0; j < (MTILE*4)/256; j++){
                int cidx = tid + j*256;
                int row = cidx >> 2, c = cidx & 3;
                CP_ASYNC16(tb + (uint32_t)(row*(LDS_E*2) + c*16),
                           bp + (size_t)row * rowbytes + c*16);
            }
        }
        {
            const char* bp = bsrc + k0bytes;
            uint32_t tb = sb + (uint32_t)(2*A_TB);
            #pragma unroll
            for (int j = 0; j < (NTILE*4)/256; j++){
                int cidx = tid + j*256;
                int row = cidx >> 2, c = cidx & 3;
                CP_ASYNC16(tb + (uint32_t)(row*(LDS_E*2) + c*16),
                           bp + (size_t)row * rowbytes + c*16);
            }
        }
        CP_COMMIT();
    };

    #pragma unroll
    for (int p = 0; p < NSTAGE - 1; p++)
        load_stage(p, p*64);

    for (int t = 0; t < nstage; t++){
        if (t + NSTAGE - 1 < nstage){
            load_stage((t + NSTAGE - 1) % NSTAGE, (t + NSTAGE - 1)*64);
            CP_WAIT(NSTAGE - 1);
        } else {
            CP_WAIT(0);
        }
        __syncthreads();

        int s = t % NSTAGE;
        const __nv_bfloat16* As_h = (const __nv_bfloat16*)(smem + s*SS);
        const __nv_bfloat16* As_l = (const __nv_bfloat16*)(smem + s*SS + A_TB);
        const __nv_bfloat16* Bs_h = (const __nv_bfloat16*)(smem + s*SS + 2*A_TB);

        #pragma unroll
        for (int kf = 0; kf < 2; kf++){
            wmma::fragment<wmma::matrix_a, 16, 16, 16, __nv_bfloat16, wmma::row_major> ah[2], al[2];
            #pragma unroll
            for (int i = 0; i < 2; i++){
                int r = wr*32 + i*16;
                wmma::load_matrix_sync(ah[i], As_h + r*LDS_E + kf*16, LDS_E);
                wmma::load_matrix_sync(al[i], As_l + r*LDS_E + kf*16, LDS_E);
            }
            #pragma unroll
            for (int j = 0; j < NJ; j++){
                wmma::fragment<wmma::matrix_b, 16, 16, 16, __nv_bfloat16, wmma::col_major> bh;
                int c = wc*WNT + j*16;
                wmma::load_matrix_sync(bh, Bs_h + c*LDS_E + kf*16, LDS_E);
                wmma::mma_sync(acc[0][j], ah[0], bh, acc[0][j]);
                wmma::mma_sync(acc[1][j], ah[1], bh, acc[1][j]);
                wmma::mma_sync(acc[0][j], al[0], bh, acc[0][j]);
                wmma::mma_sync(acc[1][j], al[1], bh, acc[1][j]);
            }
        }
        __syncthreads();
    }

    if (MODE == 0){
        #pragma unroll
        for (int i = 0; i < 2; i++)
            #pragma unroll
            for (int j = 0; j < NJ; j++){
                float* cp = C + (size_t)(m0 + wr*32 + i*16) * Nc + n0 + wc*WNT + j*16;
                wmma::store_matrix_sync(cp, acc[i][j], Nc, wmma::mem_row_major);
            }
    } else {
        float* stg = (float*)smem + (size_t)wid * (32*STGL);
        #pragma unroll
        for (int i = 0; i < 2; i++)
            #pragma unroll
            for (int j = 0; j < NJ; j++)
                wmma::store_matrix_sync(stg + i*16*STGL + j*16, acc[i][j], STGL,
                                        wmma::mem_row_major);
        __syncwarp();

        int row = m0 + wr*32 + lane;
        int h   = row / 96;
        int w2  = row - h*96;
        bool isx = (w2 < 48);
        int  w   = isx ? w2 : (w2 - 48);
        const float* rsrc = (isx ? rx : ry) + h*48 + w;
        float* od = outp + (isx ? 0 : XFSZ) + h*48 + w;
        #pragma unroll 8
        for (int j = 0; j < WNT; j++){
            int col = n0 + wc*WNT + j;
            od[(size_t)col * PLANE] = stg[lane*STGL + j] + rsrc[(size_t)col * PLANE];
        }
    }
}
// G1: 128x128, 2-stage, 2-term: SS = 30720 -> 61440 B, 2 CTAs/SM (R11 proven)
#define GEMM_SMEM_G1 (2 * (2*(128*LDS_E*2) + (128*LDS_E*2)))
// G2: 64x64, 3-stage, 2-term: SS = 15360 -> 46080 B, 3 CTAs/SM (R11 proven)
#define GEMM_SMEM_G2 (3 * (2*(64*LDS_E*2) + (64*LDS_E*2)))

// ---------------- 3) causal depthwise conv (K=4) + SiLU, 16 rows/block ----------------
__global__ void conv_silu_kernel(const float* __restrict__ cw){
    int d  = blockIdx.x * 256 + threadIdx.x;  // grid.x = 5
    int l0 = blockIdx.y * 16;                 // grid.y = 288
    float4 wv = ((const float4*)cw)[d];
    const float* xp = g_xz + d;
    float h1 = (l0 >= 1) ? xp[(size_t)(l0-1) * DXZ] : 0.f;
    float h2 = (l0 >= 2) ? xp[(size_t)(l0-2) * DXZ] : 0.f;
    float h3 = (l0 >= 3) ? xp[(size_t)(l0-3) * DXZ] : 0.f;
    #pragma unroll
    for (int i = 0; i < 16; i++){
        float v = xp[(size_t)(l0+i) * DXZ];
        float acc = wv.w*v + wv.z*h1 + wv.y*h2 + wv.x*h3;
        g_xa[(size_t)(l0+i) * DI + d] = silu_f(acc);
        h3 = h2; h2 = h1; h1 = v;
    }
}

// ---------------- 4) proj GEMM split-K=16: xa @ W_xproj ----------------
__global__ void proj_gemm(const float* __restrict__ A, const float* __restrict__ B){
    __shared__ float As[16][64];
    __shared__ float Bs[16][64];
    int tid = threadIdx.x;
    int by  = blockIdx.x;                 // 0..71
    int ks  = blockIdx.y;                 // 0..15
    int k0b = ks * 80;

    int arow = tid >> 2;
    int acol = (tid & 3) * 4;
    const float* Ap = A + (size_t)(by*64 + arow) * DI + k0b + acol;

    float acc[4][4];
    #pragma unroll
    for (int i = 0; i < 4; i++)
        #pragma unroll
        for (int j = 0; j < 4; j++) acc[i][j] = 0.f;

    int ty = tid >> 4, tx = tid & 15;

    for (int k0 = 0; k0 < 80; k0 += 16){
        float4 av = *(const float4*)Ap;
        float bl[4];
        #pragma unroll
        for (int q = 0; q < 4; q++){
            int e = tid*4 + q;
            int rr = e >> 6, c = e & 63;
            bl[q] = (c < NPROJ) ? B[(size_t)(k0b + k0 + rr) * NPROJ + c] : 0.f;
        }
        __syncthreads();
        As[acol+0][arow] = av.x;
        As[acol+1][arow] = av.y;
        As[acol+2][arow] = av.z;
        As[acol+3][arow] = av.w;
        #pragma unroll
        for (int q = 0; q < 4; q++){
            int e = tid*4 + q;
            Bs[e >> 6][e & 63] = bl[q];
        }
        __syncthreads();
        #pragma unroll
        for (int k = 0; k < 16; k++){
            float ar[4], br[4];
            #pragma unroll
            for (int i = 0; i < 4; i++) ar[i] = As[k][ty*4 + i];
            #pragma unroll
            for (int j = 0; j < 4; j++) br[j] = Bs[k][tx*4 + j];
            #pragma unroll
            for (int i = 0; i < 4; i++)
                #pragma unroll
                for (int j = 0; j < 4; j++)
                    acc[i][j] = fmaf(ar[i], br[j], acc[i][j]);
        }
        __syncthreads();
        Ap += 16;
    }
    float* Cp = g_pp + (size_t)ks * PSLICE;
    #pragma unroll
    for (int i = 0; i < 4; i++){
        int row = by*64 + ty*4 + i;
        #pragma unroll
        for (int j = 0; j < 4; j++){
            int col = tx*4 + j;
            if (col < NPROJ) Cp[(size_t)row * NPROJ + col] = acc[i][j];
        }
    }
}

__global__ void proj_reduce(){
    int i = blockIdx.x * 256 + threadIdx.x;
    if (i < PSLICE){
        float a = 0.f;
        #pragma unroll
        for (int k = 0; k < KSPLIT; k++) a += g_pp[(size_t)k * PSLICE + i];
        g_proj[i] = a;
    }
}

// ---------------- 6) chunked parallel scan; phase A computes dt inline ----------------
__global__ void __launch_bounds__(256)
scan_phaseA(const float* __restrict__ A_log,
            const float* __restrict__ Wdt, const float* __restrict__ dtbias){
    int t = threadIdx.x;
    int d = blockIdx.x * 256 + t;        // grid.x = 5
    int g = blockIdx.y;                  // 0..71

    float Wd[RANK];
    #pragma unroll
    for (int k = 0; k < RANK; k++) Wd[k] = Wdt[(size_t)k * DI + d];
    float bb = dtbias[d];

    float Ac[8];
    #pragma unroll
    for (int s = 0; s < 8; s++) Ac[s] = -__expf(A_log[d*8 + s]);
    bool fast = true;
    #pragma unroll
    for (int s = 0; s < 8; s++){
        float r = Ac[s] / Ac[0];
        if (fabsf(r - (float)(s+1)) > 1e-3f) fast = false;
    }

    float h[8];
    #pragma unroll
    for (int s = 0; s < 8; s++) h[s] = 0.f;
    float Etot = 1.f;
    float Ps[8];
    #pragma unroll
    for (int s = 0; s < 8; s++) Ps[s] = 1.f;

    const float* xap = g_xa   + (size_t)(g*CLEN) * DI + d;
    const float* prp = g_proj + (size_t)(g*CLEN) * NPROJ;
    float*       dtw = g_dt   + (size_t)(g*CLEN) * DI + d;

    for (int l = 0; l < CLEN; l++){
        // dt = softplus(proj[l,:40] . Wd + bias)  (proj loads are warp-uniform)
        float a = 0.f;
        #pragma unroll
        for (int k = 0; k < RANK; k++) a = fmaf(__ldg(prp + k), Wd[k], a);
        float v = a + bb;
        float dtv = (v > 20.f) ? v : log1pf(__expf(v));
        *dtw = dtv;

        float xav = *xap;
        float db = dtv * xav;
        const float* bp = prp + RANK;
        if (fast){
            float e1 = __expf(dtv * Ac[0]);
            Etot *= e1;
            float p = 1.f;
            #pragma unroll
            for (int s = 0; s < 8; s++){
                p *= e1;
                h[s] = fmaf(p, h[s], db * __ldg(bp + s));
            }
        } else {
            #pragma unroll
            for (int s = 0; s < 8; s++){
                float dA = __expf(dtv * Ac[s]);
                Ps[s] *= dA;
                h[s] = fmaf(dA, h[s], db * __ldg(bp + s));
            }
        }
        xap += DI; prp += NPROJ; dtw += DI;
    }
    size_t base = (size_t)g * DS + d*8;
    if (fast){
        float P = 1.f;
        #pragma unroll
        for (int s = 0; s < 8; s++){
            P *= Etot;
            g_cP[base + s] = P;
            g_cH[base + s] = h[s];
        }
    } else {
        #pragma unroll
        for (int s = 0; s < 8; s++){
            g_cP[base + s] = Ps[s];
            g_cH[base + s] = h[s];
        }
    }
}

__global__ void scan_phaseB(){
    int idx = blockIdx.x * 256 + threadIdx.x;
    float h = 0.f;
    for (int g = 0; g < NCHUNK; g++){
        size_t o = (size_t)g * DS + idx;
        g_h0[o] = h;
        h = fmaf(g_cP[o], h, g_cH[o]);
    }
}

__global__ void __launch_bounds__(256)
scan_phaseC(const float* __restrict__ A_log, const float* __restrict__ Dp){
    int t = threadIdx.x;
    int d = blockIdx.x * 256 + t;
    int g = blockIdx.y;

    float Ac[8];
    #pragma unroll
    for (int s = 0; s < 8; s++) Ac[s] = -__expf(A_log[d*8 + s]);
    bool fast = true;
    #pragma unroll
    for (int s = 0; s < 8; s++){
        float r = Ac[s] / Ac[0];
        if (fabsf(r - (float)(s+1)) > 1e-3f) fast = false;
    }

    float h[8];
    size_t hb = (size_t)g * DS + d*8;
    #pragma unroll
    for (int s = 0; s < 8; s++) h[s] = g_h0[hb + s];
    float Dval = Dp[d];

    const float* dtp = g_dt   + (size_t)(g*CLEN) * DI + d;
    const float* xap = g_xa   + (size_t)(g*CLEN) * DI + d;
    const float* zp  = g_xz   + (size_t)(g*CLEN) * DXZ + DI + d;
    const float* bp  = g_proj + (size_t)(g*CLEN) * NPROJ + RANK;
    size_t yoff = (size_t)(g*CLEN) * DI + d;

    if (fast){
        for (int l = 0; l < CLEN; l++){
            float dtv = *dtp, xav = *xap;
            float e1 = __expf(dtv * Ac[0]);
            float db = dtv * xav;
            float p = 1.f, yv = 0.f;
            #pragma unroll
            for (int s = 0; s < 8; s++){
                p *= e1;
                h[s] = fmaf(p, h[s], db * __ldg(bp + s));
                yv = fmaf(h[s], __ldg(bp + 8 + s), yv);
            }
            float val = (yv + xav * Dval) * silu_f(*zp);
            split_store(val, g_a2hi, g_a2lo, yoff);
            dtp += DI; xap += DI; zp += DXZ; bp += NPROJ; yoff += DI;
        }
    } else {
        for (int l = 0; l < CLEN; l++){
            float dtv = *dtp, xav = *xap;
            float db = dtv * xav;
            float yv = 0.f;
            #pragma unroll
            for (int s = 0; s < 8; s++){
                float dA = __expf(dtv * Ac[s]);
                h[s] = fmaf(dA, h[s], db * __ldg(bp + s));
                yv = fmaf(h[s], __ldg(bp + 8 + s), yv);
            }
            float val = (yv + xav * Dval) * silu_f(*zp);
            split_store(val, g_a2hi, g_a2lo, yoff);
            dtp += DI; xap += DI; zp += DXZ; bp += NPROJ; yoff += DI;
        }
    }
}

// ---------------- launch ----------------
extern "C" void kernel_launch(void* const* d_in, const int* in_sizes, int n_in,
                              void* d_out, int out_size){
    const float* x       = (const float*)d_in[0];
    const float* y       = (const float*)d_in[1];
    const float* ln_g    = (const float*)d_in[2];
    const float* ln_b    = (const float*)d_in[3];
    const float* W_in    = (const float*)d_in[4];
    const float* conv_w  = (const float*)d_in[5];
    const float* W_xproj = (const float*)d_in[6];
    const float* W_dt    = (const float*)d_in[7];
    const float* dt_bias = (const float*)d_in[8];
    const float* A_log   = (const float*)d_in[9];
    const float* Dp      = (const float*)d_in[10];
    const float* W_out   = (const float*)d_in[11];
    float* out = (float*)d_out;

    cudaFuncSetAttribute((const void*)gemm_wmma<0,4,128,2,2>,
                         cudaFuncAttributeMaxDynamicSharedMemorySize, GEMM_SMEM_G1);
    cudaFuncSetAttribute((const void*)gemm_wmma<1,2,64,3,3>,
                         cudaFuncAttributeMaxDynamicSharedMemorySize, GEMM_SMEM_G2);
    cudaFuncSetAttribute((const void*)ln_kernel,
                         cudaFuncAttributeMaxDynamicSharedMemorySize, LN_SMEM);

    float *xz_p, *xa_p;
    __nv_bfloat16 *a1h, *a1l, *b1h, *a2h, *a2l, *b2h;
    cudaGetSymbolAddress((void**)&xz_p, g_xz);
    cudaGetSymbolAddress((void**)&xa_p, g_xa);
    cudaGetSymbolAddress((void**)&a1h, g_a1hi);  cudaGetSymbolAddress((void**)&a1l, g_a1lo);
    cudaGetSymbolAddress((void**)&b1h, g_b1hi);
    cudaGetSymbolAddress((void**)&a2h, g_a2hi);  cudaGetSymbolAddress((void**)&a2l, g_a2lo);
    cudaGetSymbolAddress((void**)&b2h, g_b2hi);

    // weight transposes (one launch)
    transpose_both<<<2400, dim3(32,8)>>>(W_in, W_out, b1h, b2h);

    // 1) gather + layernorm -> a1 (bf16 hi/lo)
    ln_kernel<<<192, 256, LN_SMEM>>>(x, y, ln_g, ln_b);

    // 2) xz = ln(seq) @ W_in   (128x128, 2-stage, 2-term)
    gemm_wmma<0,4,128,2,2><<<dim3(DXZ/128, LSEQ/128), 256, GEMM_SMEM_G1>>>(
        a1h, a1l, b1h, xz_p, CDIM, DXZ, nullptr, nullptr, nullptr);

    // 3) xa = silu(causal_dwconv(xp)), 16 rows/block
    conv_silu_kernel<<<dim3(DI/256, LSEQ/16), 256>>>(conv_w);

    // 4) proj = xa @ W_xproj (split-K=16)
    proj_gemm<<<dim3(LSEQ/64, KSPLIT), 256>>>(xa_p, W_xproj);
    proj_reduce<<<(PSLICE + 255)/256, 256>>>();

    // 5+6) scan phase A with fused dt; then B, C
    scan_phaseA<<<dim3(DI/256, NCHUNK), 256>>>(A_log, W_dt, dt_bias);
    scan_phaseB<<<DS/256, 256>>>();
    scan_phaseC<<<dim3(DI/256, NCHUNK), 256>>>(A_log, Dp);

    // 7) out = yo @ W_out + seq  (64x64, 3-stage, 2-term, fused residual+scatter)
    gemm_wmma<1,2,64,3,3><<<dim3(CDIM/64, LSEQ/64), 256, GEMM_SMEM_G2>>>(
        a2h, a2l, b2h, nullptr, DI, CDIM, x, y, out);
}

// round 14
// speedup vs baseline: 1.1787x; 1.1787x over previous
#include <cuda_runtime.h>
#include <cuda_bf16.h>
#include <mma.h>
#include <cstdint>

using namespace nvcuda;

#define LSEQ 4608
#define CDIM 640
#define DI   1280
#define DXZ  2560
#define NPROJ 56
#define RANK  40
#define PLANE 2304          // 48*48
#define XFSZ  (640*2304)
#define PSLICE (LSEQ*NPROJ)
#define NCHUNK 72
#define CLEN   64
#define DS     (DI*8)
#define KSPLIT 16

// ---------------- scratch ----------------
__device__ float g_xz  [LSEQ*DXZ];
__device__ float g_xa  [LSEQ*DI];
__device__ float g_proj[LSEQ*NPROJ];
__device__ float g_pp  [KSPLIT*PSLICE];
__device__ float g_dt  [LSEQ*DI];
__device__ float g_cP  [NCHUNK*DS];
__device__ float g_cH  [NCHUNK*DS];
__device__ float g_h0  [NCHUNK*DS];
// bf16 operands: activations get hi/lo split; weights hi only (2-term scheme)
__device__ __align__(256) __nv_bfloat16 g_a1hi[LSEQ*CDIM], g_a1lo[LSEQ*CDIM]; // ln(seq)
__device__ __align__(256) __nv_bfloat16 g_b1hi[DXZ*CDIM];                     // W_in^T
__device__ __align__(256) __nv_bfloat16 g_a2hi[LSEQ*DI],   g_a2lo[LSEQ*DI];   // yo
__device__ __align__(256) __nv_bfloat16 g_b2hi[CDIM*DI];                      // W_out^T

// ---------------- helpers ----------------
#define CP_ASYNC16(dst, src) \
    asm volatile("cp.async.cg.shared.global [%0], [%1], 16;" :: "r"(dst), "l"(src) : "memory")
#define CP_COMMIT() asm volatile("cp.async.commit_group;" ::: "memory")
#define CP_WAIT(n)  asm volatile("cp.async.wait_group %0;" :: "n"(n) : "memory")

__device__ __forceinline__ uint32_t smem_u32(const void* p){
    uint32_t a;
    asm("{ .reg .u64 t; cvta.to.shared.u64 t, %1; cvt.u32.u64 %0, t; }" : "=r"(a) : "l"(p));
    return a;
}
__device__ __forceinline__ float silu_f(float v){ return v / (1.0f + __expf(-v)); }
__device__ __forceinline__ void split_store(float v, __nv_bfloat16* hi, __nv_bfloat16* lo, size_t off){
    __nv_bfloat16 h = __float2bfloat16(v);
    hi[off] = h;
    lo[off] = __float2bfloat16(v - __bfloat162float(h));
}

// ---------------- 1) gather + layernorm -> bf16 hi/lo (coalesced via smem transpose) ----
#define LN_SMEM ((16000 + 640 + 640) * 4)
__global__ void __launch_bounds__(256)
ln_kernel(const float* __restrict__ x, const float* __restrict__ yy,
          const float* __restrict__ g, const float* __restrict__ b){
    extern __shared__ float sm[];             // T[640*25] | gg[640] | bb[640]
    float* T  = sm;
    float* gg = sm + 16000;
    float* bb = sm + 16640;
    int bid = blockIdx.x;                     // 0..191
    bool isx = bid < 96;
    int hb = bid - (isx ? 0 : 96);
    int h  = hb >> 1;
    int w0 = (hb & 1) * 24;
    const float* src = (isx ? x : yy) + h*48 + w0;
    int tid = threadIdx.x;

    for (int e = tid; e < 640; e += 256){ gg[e] = g[e]; bb[e] = b[e]; }
    for (int e = tid; e < 15360; e += 256){
        int c = e / 24, w = e - c*24;
        T[c*25 + w] = src[(size_t)c * PLANE + w];
    }
    __syncthreads();

    int wid = tid >> 5, lane = tid & 31;
    #pragma unroll
    for (int pi = 0; pi < 3; pi++){
        int p = wid + pi*8;                   // 0..23
        float s = 0.f, s2 = 0.f;
        #pragma unroll
        for (int k = 0; k < 20; k++){
            float v = T[(lane + k*32)*25 + p];
            s += v; s2 += v*v;
        }
        #pragma unroll
        for (int o = 16; o; o >>= 1){
            s  += __shfl_xor_sync(0xffffffffu, s , o);
            s2 += __shfl_xor_sync(0xffffffffu, s2, o);
        }
        float mean = s  * (1.f/640.f);
        float var  = s2 * (1.f/640.f) - mean*mean;
        float inv  = rsqrtf(var + 1e-5f);
        int l = h*96 + (isx ? 0 : 48) + w0 + p;
        size_t base = (size_t)l * CDIM;
        #pragma unroll
        for (int k = 0; k < 20; k++){
            int c = lane + k*32;
            float o = (T[c*25 + p] - mean) * inv * gg[c] + bb[c];
            split_store(o, g_a1hi, g_a1lo, base + c);
        }
    }
}

// ---------------- weight transposes (both) + bf16 hi: W[K,N] -> Wt[n*K+k] ----------------
// blocks [0,1600): W_in (640x2560); blocks [1600,2400): W_out (1280x640)
__global__ void transpose_both(const float* __restrict__ Wi, const float* __restrict__ Wo,
                               __nv_bfloat16* __restrict__ b1h, __nv_bfloat16* __restrict__ b2h){
    __shared__ float tile[32][33];
    int id = blockIdx.x;
    const float* W; __nv_bfloat16* hi; int K, N, bx, by;
    if (id < 1600){ W = Wi; hi = b1h; K = CDIM; N = DXZ; bx = id % 80; by = id / 80; }
    else { int j = id - 1600; W = Wo; hi = b2h; K = DI; N = CDIM; bx = j % 20; by = j / 20; }
    int n0 = bx * 32, k0 = by * 32;
    int tx = threadIdx.x, ty = threadIdx.y;   // (32, 8)
    #pragma unroll
    for (int i = 0; i < 4; i++)
        tile[ty + 8*i][tx] = W[(size_t)(k0 + ty + 8*i) * N + n0 + tx];
    __syncthreads();
    #pragma unroll
    for (int i = 0; i < 4; i++){
        float v = tile[tx][ty + 8*i];
        hi[(size_t)(n0 + ty + 8*i) * K + k0 + tx] = __float2bfloat16(v);
    }
}

// ---------------- wmma 2-term bf16-split GEMM: C = (Ahi+Alo) @ Bhi^T ----------------
#define LDS_E 40                         // bf16 smem row stride (80B)

template<int MODE, int MW, int NTILE, int NSTAGE, int MAXB>
__global__ void __launch_bounds__(256, MAXB)
gemm_wmma(const __nv_bfloat16* __restrict__ Ahi, const __nv_bfloat16* __restrict__ Alo,
          const __nv_bfloat16* __restrict__ Bhi,
          float* __restrict__ C, int K, int Nc,
          const float* __restrict__ rx, const float* __restrict__ ry,
          float* __restrict__ outp){
    constexpr int MTILE = MW * 32;
    constexpr int NW    = 8 / MW;
    constexpr int WNT   = NTILE / NW;
    constexpr int NJ    = WNT / 16;
    constexpr int A_TB  = MTILE * LDS_E * 2;
    constexpr int B_TB  = NTILE * LDS_E * 2;
    constexpr int SS    = 2*A_TB + B_TB;
    constexpr int STGL  = WNT + 4;

    extern __shared__ __align__(32) char smem[];
    uint32_t sbase = smem_u32(smem);
    int tid = threadIdx.x;
    int wid = tid >> 5, lane = tid & 31;
    int wr = wid % MW, wc = wid / MW;
    int n0 = blockIdx.x * NTILE, m0 = blockIdx.y * MTILE;

    const char* asrc[2] = {
        (const char*)(Ahi + (size_t)m0 * K), (const char*)(Alo + (size_t)m0 * K) };
    const char* bsrc = (const char*)(Bhi + (size_t)n0 * K);
    int rowbytes = K * 2;
    int nstage = K / 32;

    wmma::fragment<wmma::accumulator, 16, 16, 16, float> acc[2][NJ];
    #pragma unroll
    for (int i = 0; i < 2; i++)
        #pragma unroll
        for (int j = 0; j < NJ; j++) wmma::fill_fragment(acc[i][j], 0.f);

    auto load_stage = [&](int st, int k0bytes){
        uint32_t sb = sbase + (uint32_t)(st * SS);
        #pragma unroll
        for (int tl = 0; tl < 2; tl++){
            const char* bp = asrc[tl] + k0bytes;
            uint32_t tb = sb + (uint32_t)(tl * A_TB);
            #pragma unroll
            for (int j = 0; j < (MTILE*4)/256; j++){
                int cidx = tid + j*256;
                int row = cidx >> 2, c = cidx & 3;
                CP_ASYNC16(tb + (uint32_t)(row*(LDS_E*2) + c*16),
                           bp + (size_t)row * rowbytes + c*16);
            }
        }
        {
            const char* bp = bsrc + k0bytes;
            uint32_t tb = sb + (uint32_t)(2*A_TB);
            #pragma unroll
            for (int j = 0; j < (NTILE*4)/256; j++){
                int cidx = tid + j*256;
                int row = cidx >> 2, c = cidx & 3;
                CP_ASYNC16(tb + (uint32_t)(row*(LDS_E*2) + c*16),
                           bp + (size_t)row * rowbytes + c*16);
            }
        }
        CP_COMMIT();
    };

    #pragma unroll
    for (int p = 0; p < NSTAGE - 1; p++)
        load_stage(p, p*64);

    for (int t = 0; t < nstage; t++){
        if (t + NSTAGE - 1 < nstage){
            load_stage((t + NSTAGE - 1) % NSTAGE, (t + NSTAGE - 1)*64);
            CP_WAIT(NSTAGE - 1);
        } else {
            CP_WAIT(0);
        }
        __syncthreads();

        int s = t % NSTAGE;
        const __nv_bfloat16* As_h = (const __nv_bfloat16*)(smem + s*SS);
        const __nv_bfloat16* As_l = (const __nv_bfloat16*)(smem + s*SS + A_TB);
        const __nv_bfloat16* Bs_h = (const __nv_bfloat16*)(smem + s*SS + 2*A_TB);

        #pragma unroll
        for (int kf = 0; kf < 2; kf++){
            wmma::fragment<wmma::matrix_a, 16, 16, 16, __nv_bfloat16, wmma::row_major> ah[2], al[2];
            #pragma unroll
            for (int i = 0; i < 2; i++){
                int r = wr*32 + i*16;
                wmma::load_matrix_sync(ah[i], As_h + r*LDS_E + kf*16, LDS_E);
                wmma::load_matrix_sync(al[i], As_l + r*LDS_E + kf*16, LDS_E);
            }
            #pragma unroll
            for (int j = 0; j < NJ; j++){
                wmma::fragment<wmma::matrix_b, 16, 16, 16, __nv_bfloat16, wmma::col_major> bh;
                int c = wc*WNT + j*16;
                wmma::load_matrix_sync(bh, Bs_h + c*LDS_E + kf*16, LDS_E);
                wmma::mma_sync(acc[0][j], ah[0], bh, acc[0][j]);
                wmma::mma_sync(acc[1][j], ah[1], bh, acc[1][j]);
                wmma::mma_sync(acc[0][j], al[0], bh, acc[0][j]);
                wmma::mma_sync(acc[1][j], al[1], bh, acc[1][j]);
            }
        }
        __syncthreads();
    }

    if (MODE == 0){
        #pragma unroll
        for (int i = 0; i < 2; i++)
            #pragma unroll
            for (int j = 0; j < NJ; j++){
                float* cp = C + (size_t)(m0 + wr*32 + i*16) * Nc + n0 + wc*WNT + j*16;
                wmma::store_matrix_sync(cp, acc[i][j], Nc, wmma::mem_row_major);
            }
    } else {
        float* stg = (float*)smem + (size_t)wid * (32*STGL);
        #pragma unroll
        for (int i = 0; i < 2; i++)
            #pragma unroll
            for (int j = 0; j < NJ; j++)
                wmma::store_matrix_sync(stg + i*16*STGL + j*16, acc[i][j], STGL,
                                        wmma::mem_row_major);
        __syncwarp();

        int row = m0 + wr*32 + lane;
        int h   = row / 96;
        int w2  = row - h*96;
        bool isx = (w2 < 48);
        int  w   = isx ? w2 : (w2 - 48);
        const float* rsrc = (isx ? rx : ry) + h*48 + w;
        float* od = outp + (isx ? 0 : XFSZ) + h*48 + w;
        #pragma unroll 8
        for (int j = 0; j < WNT; j++){
            int col = n0 + wc*WNT + j;
            od[(size_t)col * PLANE] = stg[lane*STGL + j] + rsrc[(size_t)col * PLANE];
        }
    }
}
// G1: 128x128, 2-stage, 2-term: SS = 30720 -> 61440 B, 2 CTAs/SM (R11 proven)
#define GEMM_SMEM_G1 (2 * (2*(128*LDS_E*2) + (128*LDS_E*2)))
// G2: 64x64, 3-stage, 2-term: SS = 15360 -> 46080 B, 3 CTAs/SM (R11 proven)
#define GEMM_SMEM_G2 (3 * (2*(64*LDS_E*2) + (64*LDS_E*2)))

// ---------------- 3) causal depthwise conv (K=4) + SiLU, 16 rows/block ----------------
__global__ void conv_silu_kernel(const float* __restrict__ cw){
    int d  = blockIdx.x * 256 + threadIdx.x;  // grid.x = 5
    int l0 = blockIdx.y * 16;                 // grid.y = 288
    float4 wv = ((const float4*)cw)[d];
    const float* xp = g_xz + d;
    float h1 = (l0 >= 1) ? xp[(size_t)(l0-1) * DXZ] : 0.f;
    float h2 = (l0 >= 2) ? xp[(size_t)(l0-2) * DXZ] : 0.f;
    float h3 = (l0 >= 3) ? xp[(size_t)(l0-3) * DXZ] : 0.f;
    #pragma unroll
    for (int i = 0; i < 16; i++){
        float v = xp[(size_t)(l0+i) * DXZ];
        float acc = wv.w*v + wv.z*h1 + wv.y*h2 + wv.x*h3;
        g_xa[(size_t)(l0+i) * DI + d] = silu_f(acc);
        h3 = h2; h2 = h1; h1 = v;
    }
}

// ---------------- 4) proj GEMM split-K=16: xa @ W_xproj ----------------
__global__ void proj_gemm(const float* __restrict__ A, const float* __restrict__ B){
    __shared__ float As[16][64];
    __shared__ float Bs[16][64];
    int tid = threadIdx.x;
    int by  = blockIdx.x;                 // 0..71
    int ks  = blockIdx.y;                 // 0..15
    int k0b = ks * 80;

    int arow = tid >> 2;
    int acol = (tid & 3) * 4;
    const float* Ap = A + (size_t)(by*64 + arow) * DI + k0b + acol;

    float acc[4][4];
    #pragma unroll
    for (int i = 0; i < 4; i++)
        #pragma unroll
        for (int j = 0; j < 4; j++) acc[i][j] = 0.f;

    int ty = tid >> 4, tx = tid & 15;

    for (int k0 = 0; k0 < 80; k0 += 16){
        float4 av = *(const float4*)Ap;
        float bl[4];
        #pragma unroll
        for (int q = 0; q < 4; q++){
            int e = tid*4 + q;
            int rr = e >> 6, c = e & 63;
            bl[q] = (c < NPROJ) ? B[(size_t)(k0b + k0 + rr) * NPROJ + c] : 0.f;
        }
        __syncthreads();
        As[acol+0][arow] = av.x;
        As[acol+1][arow] = av.y;
        As[acol+2][arow] = av.z;
        As[acol+3][arow] = av.w;
        #pragma unroll
        for (int q = 0; q < 4; q++){
            int e = tid*4 + q;
            Bs[e >> 6][e & 63] = bl[q];
        }
        __syncthreads();
        #pragma unroll
        for (int k = 0; k < 16; k++){
            float ar[4], br[4];
            #pragma unroll
            for (int i = 0; i < 4; i++) ar[i] = As[k][ty*4 + i];
            #pragma unroll
            for (int j = 0; j < 4; j++) br[j] = Bs[k][tx*4 + j];
            #pragma unroll
            for (int i = 0; i < 4; i++)
                #pragma unroll
                for (int j = 0; j < 4; j++)
                    acc[i][j] = fmaf(ar[i], br[j], acc[i][j]);
        }
        __syncthreads();
        Ap += 16;
    }
    float* Cp = g_pp + (size_t)ks * PSLICE;
    #pragma unroll
    for (int i = 0; i < 4; i++){
        int row = by*64 + ty*4 + i;
        #pragma unroll
        for (int j = 0; j < 4; j++){
            int col = tx*4 + j;
            if (col < NPROJ) Cp[(size_t)row * NPROJ + col] = acc[i][j];
        }
    }
}

__global__ void proj_reduce(){
    int i = blockIdx.x * 256 + threadIdx.x;
    if (i < PSLICE){
        float a = 0.f;
        #pragma unroll
        for (int k = 0; k < KSPLIT; k++) a += g_pp[(size_t)k * PSLICE + i];
        g_proj[i] = a;
    }
}

// ---------------- 5) dt = softplus(proj[:, :40] @ W_dt + bias), 16 rows/block ------
__global__ void dt_kernel(const float* __restrict__ Wdt, const float* __restrict__ bias){
    __shared__ float pr[16][RANK];
    int t  = threadIdx.x;
    int d  = blockIdx.x * 256 + t;       // grid.x = 5
    int l0 = blockIdx.y * 16;            // grid.y = 288
    for (int e = t; e < 16*RANK; e += 256)
        pr[e / RANK][e % RANK] = g_proj[(size_t)(l0 + e / RANK) * NPROJ + (e % RANK)];
    __syncthreads();

    float acc[16];
    #pragma unroll
    for (int j = 0; j < 16; j++) acc[j] = 0.f;
    for (int k = 0; k < RANK; k++){
        float wv = Wdt[(size_t)k * DI + d];
        #pragma unroll
        for (int j = 0; j < 16; j++) acc[j] = fmaf(pr[j][k], wv, acc[j]);
    }
    float bb = bias[d];
    #pragma unroll
    for (int j = 0; j < 16; j++){
        float v = acc[j] + bb;
        float sp = (v > 20.f) ? v : log1pf(__expf(v));
        g_dt[(size_t)(l0 + j) * DI + d] = sp;
    }
}

// ---------------- 6) chunked parallel scan (72 x 64) ----------------
__global__ void __launch_bounds__(256)
scan_phaseA(const float* __restrict__ A_log){
    int t = threadIdx.x;
    int d = blockIdx.x * 256 + t;
    int g = blockIdx.y;

    float Ac[8];
    #pragma unroll
    for (int s = 0; s < 8; s++) Ac[s] = -__expf(A_log[d*8 + s]);
    bool fast = true;
    #pragma unroll
    for (int s = 0; s < 8; s++){
        float r = Ac[s] / Ac[0];
        if (fabsf(r - (float)(s+1)) > 1e-3f) fast = false;
    }

    float h[8];
    #pragma unroll
    for (int s = 0; s < 8; s++) h[s] = 0.f;
    float Etot = 1.f;

    const float* dtp = g_dt   + (size_t)(g*CLEN) * DI + d;
    const float* xap = g_xa   + (size_t)(g*CLEN) * DI + d;
    const float* bp  = g_proj + (size_t)(g*CLEN) * NPROJ + RANK;

    if (fast){
        for (int l = 0; l < CLEN; l++){
            float dtv = *dtp, xav = *xap;
            float e1 = __expf(dtv * Ac[0]);
            float db = dtv * xav;
            Etot *= e1;
            float p = 1.f;
            #pragma unroll
            for (int s = 0; s < 8; s++){
                p *= e1;
                h[s] = fmaf(p, h[s], db * __ldg(bp + s));
            }
            dtp += DI; xap += DI; bp += NPROJ;
        }
        size_t base = (size_t)g * DS + d*8;
        float P = 1.f;
        #pragma unroll
        for (int s = 0; s < 8; s++){
            P *= Etot;
            g_cP[base + s] = P;
            g_cH[base + s] = h[s];
        }
    } else {
        float Ps[8];
        #pragma unroll
        for (int s = 0; s < 8; s++) Ps[s] = 1.f;
        for (int l = 0; l < CLEN; l++){
            float dtv = *dtp, xav = *xap;
            float db = dtv * xav;
            #pragma unroll
            for (int s = 0; s < 8; s++){
                float dA = __expf(dtv * Ac[s]);
                Ps[s] *= dA;
                h[s] = fmaf(dA, h[s], db * __ldg(bp + s));
            }
            dtp += DI; xap += DI; bp += NPROJ;
        }
        size_t base = (size_t)g * DS + d*8;
        #pragma unroll
        for (int s = 0; s < 8; s++){
            g_cP[base + s] = Ps[s];
            g_cH[base + s] = h[s];
        }
    }
}

__global__ void scan_phaseB(){
    int idx = blockIdx.x * 256 + threadIdx.x;
    float h = 0.f;
    for (int g = 0; g < NCHUNK; g++){
        size_t o = (size_t)g * DS + idx;
        g_h0[o] = h;
        h = fmaf(g_cP[o], h, g_cH[o]);
    }
}

__global__ void __launch_bounds__(256)
scan_phaseC(const float* __restrict__ A_log, const float* __restrict__ Dp){
    int t = threadIdx.x;
    int d = blockIdx.x * 256 + t;
    int g = blockIdx.y;

    float Ac[8];
    #pragma unroll
    for (int s = 0; s < 8; s++) Ac[s] = -__expf(A_log[d*8 + s]);
    bool fast = true;
    #pragma unroll
    for (int s = 0; s < 8; s++){
        float r = Ac[s] / Ac[0];
        if (fabsf(r - (float)(s+1)) > 1e-3f) fast = false;
    }

    float h[8];
    size_t hb = (size_t)g * DS + d*8;
    #pragma unroll
    for (int s = 0; s < 8; s++) h[s] = g_h0[hb + s];
    float Dval = Dp[d];

    const float* dtp = g_dt   + (size_t)(g*CLEN) * DI + d;
    const float* xap = g_xa   + (size_t)(g*CLEN) * DI + d;
    const float* zp  = g_xz   + (size_t)(g*CLEN) * DXZ + DI + d;
    const float* bp  = g_proj + (size_t)(g*CLEN) * NPROJ + RANK;
    size_t yoff = (size_t)(g*CLEN) * DI + d;

    if (fast){
        for (int l = 0; l < CLEN; l++){
            float dtv = *dtp, xav = *xap;
            float e1 = __expf(dtv * Ac[0]);
            float db = dtv * xav;
            float p = 1.f, yv = 0.f;
            #pragma unroll
            for (int s = 0; s < 8; s++){
                p *= e1;
                h[s] = fmaf(p, h[s], db * __ldg(bp + s));
                yv = fmaf(h[s], __ldg(bp + 8 + s), yv);
            }
            float val = (yv + xav * Dval) * silu_f(*zp);
            split_store(val, g_a2hi, g_a2lo, yoff);
            dtp += DI; xap += DI; zp += DXZ; bp += NPROJ; yoff += DI;
        }
    } else {
        for (int l = 0; l < CLEN; l++){
            float dtv = *dtp, xav = *xap;
            float db = dtv * xav;
            float yv = 0.f;
            #pragma unroll
            for (int s = 0; s < 8; s++){
                float dA = __expf(dtv * Ac[s]);
                h[s] = fmaf(dA, h[s], db * __ldg(bp + s));
                yv = fmaf(h[s], __ldg(bp + 8 + s), yv);
            }
            float val = (yv + xav * Dval) * silu_f(*zp);
            split_store(val, g_a2hi, g_a2lo, yoff);
            dtp += DI; xap += DI; zp += DXZ; bp += NPROJ; yoff += DI;
        }
    }
}

// ---------------- launch ----------------
extern "C" void kernel_launch(void* const* d_in, const int* in_sizes, int n_in,
                              void* d_out, int out_size){
    const float* x       = (const float*)d_in[0];
    const float* y       = (const float*)d_in[1];
    const float* ln_g    = (const float*)d_in[2];
    const float* ln_b    = (const float*)d_in[3];
    const float* W_in    = (const float*)d_in[4];
    const float* conv_w  = (const float*)d_in[5];
    const float* W_xproj = (const float*)d_in[6];
    const float* W_dt    = (const float*)d_in[7];
    const float* dt_bias = (const float*)d_in[8];
    const float* A_log   = (const float*)d_in[9];
    const float* Dp      = (const float*)d_in[10];
    const float* W_out   = (const float*)d_in[11];
    float* out = (float*)d_out;

    cudaFuncSetAttribute((const void*)gemm_wmma<0,4,128,2,2>,
                         cudaFuncAttributeMaxDynamicSharedMemorySize, GEMM_SMEM_G1);
    cudaFuncSetAttribute((const void*)gemm_wmma<1,2,64,3,3>,
                         cudaFuncAttributeMaxDynamicSharedMemorySize, GEMM_SMEM_G2);
    cudaFuncSetAttribute((const void*)ln_kernel,
                         cudaFuncAttributeMaxDynamicSharedMemorySize, LN_SMEM);

    float *xz_p, *xa_p;
    __nv_bfloat16 *a1h, *a1l, *b1h, *a2h, *a2l, *b2h;
    cudaGetSymbolAddress((void**)&xz_p, g_xz);
    cudaGetSymbolAddress((void**)&xa_p, g_xa);
    cudaGetSymbolAddress((void**)&a1h, g_a1hi);  cudaGetSymbolAddress((void**)&a1l, g_a1lo);
    cudaGetSymbolAddress((void**)&b1h, g_b1hi);
    cudaGetSymbolAddress((void**)&a2h, g_a2hi);  cudaGetSymbolAddress((void**)&a2l, g_a2lo);
    cudaGetSymbolAddress((void**)&b2h, g_b2hi);

    // weight transposes (one launch, bf16 hi only)
    transpose_both<<<2400, dim3(32,8)>>>(W_in, W_out, b1h, b2h);

    // 1) gather + layernorm -> a1 (bf16 hi/lo)
    ln_kernel<<<192, 256, LN_SMEM>>>(x, y, ln_g, ln_b);

    // 2) xz = ln(seq) @ W_in   (128x128, 2-stage, 2-term)
    gemm_wmma<0,4,128,2,2><<<dim3(DXZ/128, LSEQ/128), 256, GEMM_SMEM_G1>>>(
        a1h, a1l, b1h, xz_p, CDIM, DXZ, nullptr, nullptr, nullptr);

    // 3) xa = silu(causal_dwconv(xp)), 16 rows/block
    conv_silu_kernel<<<dim3(DI/256, LSEQ/16), 256>>>(conv_w);

    // 4) proj = xa @ W_xproj (split-K=16)
    proj_gemm<<<dim3(LSEQ/64, KSPLIT), 256>>>(xa_p, W_xproj);
    proj_reduce<<<(PSLICE + 255)/256, 256>>>();

    // 5) dt (16 rows/block)
    dt_kernel<<<dim3(DI/256, LSEQ/16), 256>>>(W_dt, dt_bias);

    // 6) chunked parallel scan (72 x 64) + gating -> a2 (bf16 hi/lo)
    scan_phaseA<<<dim3(DI/256, NCHUNK), 256>>>(A_log);
    scan_phaseB<<<DS/256, 256>>>();
    scan_phaseC<<<dim3(DI/256, NCHUNK), 256>>>(A_log, Dp);

    // 7) out = yo @ W_out + seq  (64x64, 3-stage, 2-term, fused residual+scatter)
    gemm_wmma<1,2,64,3,3><<<dim3(CDIM/64, LSEQ/64), 256, GEMM_SMEM_G2>>>(
        a2h, a2l, b2h, nullptr, DI, CDIM, x, y, out);
}

// round 15
// speedup vs baseline: 1.4823x; 1.2576x over previous
#include <cuda_runtime.h>
#include <cuda_bf16.h>
#include <mma.h>
#include <cstdint>

using namespace nvcuda;

#define LSEQ 4608
#define CDIM 640
#define DI   1280
#define DXZ  2560
#define NPROJ 56
#define RANK  40
#define PLANE 2304          // 48*48
#define XFSZ  (640*2304)
#define PSLICE (LSEQ*NPROJ)
#define NCHUNK 72
#define CLEN   64
#define DS     (DI*8)
#define KSPLIT 16

// ---------------- scratch ----------------
__device__ float g_xz  [LSEQ*DXZ];
__device__ float g_xa  [LSEQ*DI];
__device__ float g_proj[LSEQ*NPROJ];
__device__ float g_pp  [KSPLIT*PSLICE];
__device__ float g_dt  [LSEQ*DI];
__device__ float g_cP  [NCHUNK*DS];
__device__ float g_cH  [NCHUNK*DS];
__device__ float g_h0  [NCHUNK*DS];
// bf16 operands (1-term scheme: bf16 A x bf16 W)
__device__ __align__(256) __nv_bfloat16 g_a1hi[LSEQ*CDIM];   // ln(seq)
__device__ __align__(256) __nv_bfloat16 g_b1hi[DXZ*CDIM];    // W_in^T
__device__ __align__(256) __nv_bfloat16 g_a2hi[LSEQ*DI];     // yo
__device__ __align__(256) __nv_bfloat16 g_b2hi[CDIM*DI];     // W_out^T

// ---------------- helpers ----------------
#define CP_ASYNC16(dst, src) \
    asm volatile("cp.async.cg.shared.global [%0], [%1], 16;" :: "r"(dst), "l"(src) : "memory")
#define CP_COMMIT() asm volatile("cp.async.commit_group;" ::: "memory")
#define CP_WAIT(n)  asm volatile("cp.async.wait_group %0;" :: "n"(n) : "memory")

__device__ __forceinline__ uint32_t smem_u32(const void* p){
    uint32_t a;
    asm("{ .reg .u64 t; cvta.to.shared.u64 t, %1; cvt.u32.u64 %0, t; }" : "=r"(a) : "l"(p));
    return a;
}
__device__ __forceinline__ float silu_f(float v){ return v / (1.0f + __expf(-v)); }

// ---------------- 1) gather + layernorm -> bf16 (coalesced via smem transpose) ----
#define LN_SMEM ((16000 + 640 + 640) * 4)
__global__ void __launch_bounds__(256)
ln_kernel(const float* __restrict__ x, const float* __restrict__ yy,
          const float* __restrict__ g, const float* __restrict__ b){
    extern __shared__ float sm[];             // T[640*25] | gg[640] | bb[640]
    float* T  = sm;
    float* gg = sm + 16000;
    float* bb = sm + 16640;
    int bid = blockIdx.x;                     // 0..191
    bool isx = bid < 96;
    int hb = bid - (isx ? 0 : 96);
    int h  = hb >> 1;
    int w0 = (hb & 1) * 24;
    const float* src = (isx ? x : yy) + h*48 + w0;
    int tid = threadIdx.x;

    for (int e = tid; e < 640; e += 256){ gg[e] = g[e]; bb[e] = b[e]; }
    for (int e = tid; e < 15360; e += 256){
        int c = e / 24, w = e - c*24;
        T[c*25 + w] = src[(size_t)c * PLANE + w];
    }
    __syncthreads();

    int wid = tid >> 5, lane = tid & 31;
    #pragma unroll
    for (int pi = 0; pi < 3; pi++){
        int p = wid + pi*8;                   // 0..23
        float s = 0.f, s2 = 0.f;
        #pragma unroll
        for (int k = 0; k < 20; k++){
            float v = T[(lane + k*32)*25 + p];
            s += v; s2 += v*v;
        }
        #pragma unroll
        for (int o = 16; o; o >>= 1){
            s  += __shfl_xor_sync(0xffffffffu, s , o);
            s2 += __shfl_xor_sync(0xffffffffu, s2, o);
        }
        float mean = s  * (1.f/640.f);
        float var  = s2 * (1.f/640.f) - mean*mean;
        float inv  = rsqrtf(var + 1e-5f);
        int l = h*96 + (isx ? 0 : 48) + w0 + p;
        size_t base = (size_t)l * CDIM;
        #pragma unroll
        for (int k = 0; k < 20; k++){
            int c = lane + k*32;
            float o = (T[c*25 + p] - mean) * inv * gg[c] + bb[c];
            g_a1hi[base + c] = __float2bfloat16(o);
        }
    }
}

// ---------------- weight transposes (both) + bf16 hi: W[K,N] -> Wt[n*K+k] ----------------
// blocks [0,1600): W_in (640x2560); blocks [1600,2400): W_out (1280x640)
__global__ void transpose_both(const float* __restrict__ Wi, const float* __restrict__ Wo,
                               __nv_bfloat16* __restrict__ b1h, __nv_bfloat16* __restrict__ b2h){
    __shared__ float tile[32][33];
    int id = blockIdx.x;
    const float* W; __nv_bfloat16* hi; int K, N, bx, by;
    if (id < 1600){ W = Wi; hi = b1h; K = CDIM; N = DXZ; bx = id % 80; by = id / 80; }
    else { int j = id - 1600; W = Wo; hi = b2h; K = DI; N = CDIM; bx = j % 20; by = j / 20; }
    int n0 = bx * 32, k0 = by * 32;
    int tx = threadIdx.x, ty = threadIdx.y;   // (32, 8)
    #pragma unroll
    for (int i = 0; i < 4; i++)
        tile[ty + 8*i][tx] = W[(size_t)(k0 + ty + 8*i) * N + n0 + tx];
    __syncthreads();
    #pragma unroll
    for (int i = 0; i < 4; i++){
        float v = tile[tx][ty + 8*i];
        hi[(size_t)(n0 + ty + 8*i) * K + k0 + tx] = __float2bfloat16(v);
    }
}

// ---------------- wmma 1-term bf16 GEMM: C = A @ B^T (both bf16, fp32 accum) ---------
#define LDS_E 40                         // bf16 smem row stride (80B)

template<int MODE, int MW, int NTILE, int NSTAGE, int MAXB>
__global__ void __launch_bounds__(256, MAXB)
gemm_wmma(const __nv_bfloat16* __restrict__ A, const __nv_bfloat16* __restrict__ Bhi,
          float* __restrict__ C, int K, int Nc,
          const float* __restrict__ rx, const float* __restrict__ ry,
          float* __restrict__ outp){
    constexpr int MTILE = MW * 32;
    constexpr int NW    = 8 / MW;
    constexpr int WNT   = NTILE / NW;
    constexpr int NJ    = WNT / 16;
    constexpr int A_TB  = MTILE * LDS_E * 2;
    constexpr int B_TB  = NTILE * LDS_E * 2;
    constexpr int SS    = A_TB + B_TB;        // per-stage bytes (A, Bhi)
    constexpr int STGL  = WNT + 4;

    extern __shared__ __align__(32) char smem[];
    uint32_t sbase = smem_u32(smem);
    int tid = threadIdx.x;
    int wid = tid >> 5, lane = tid & 31;
    int wr = wid % MW, wc = wid / MW;
    int n0 = blockIdx.x * NTILE, m0 = blockIdx.y * MTILE;

    const char* asrc = (const char*)(A   + (size_t)m0 * K);
    const char* bsrc = (const char*)(Bhi + (size_t)n0 * K);
    int rowbytes = K * 2;
    int nstage = K / 32;

    wmma::fragment<wmma::accumulator, 16, 16, 16, float> acc[2][NJ];
    #pragma unroll
    for (int i = 0; i < 2; i++)
        #pragma unroll
        for (int j = 0; j < NJ; j++) wmma::fill_fragment(acc[i][j], 0.f);

    auto load_stage = [&](int st, int k0bytes){
        uint32_t sb = sbase + (uint32_t)(st * SS);
        {
            const char* bp = asrc + k0bytes;
            #pragma unroll
            for (int j = 0; j < (MTILE*4)/256; j++){
                int cidx = tid + j*256;
                int row = cidx >> 2, c = cidx & 3;
                CP_ASYNC16(sb + (uint32_t)(row*(LDS_E*2) + c*16),
                           bp + (size_t)row * rowbytes + c*16);
            }
        }
        {
            const char* bp = bsrc + k0bytes;
            uint32_t tb = sb + (uint32_t)A_TB;
            #pragma unroll
            for (int j = 0; j < (NTILE*4)/256; j++){
                int cidx = tid + j*256;
                int row = cidx >> 2, c = cidx & 3;
                CP_ASYNC16(tb + (uint32_t)(row*(LDS_E*2) + c*16),
                           bp + (size_t)row * rowbytes + c*16);
            }
        }
        CP_COMMIT();
    };

    #pragma unroll
    for (int p = 0; p < NSTAGE - 1; p++)
        load_stage(p, p*64);

    for (int t = 0; t < nstage; t++){
        if (t + NSTAGE - 1 < nstage){
            load_stage((t + NSTAGE - 1) % NSTAGE, (t + NSTAGE - 1)*64);
            CP_WAIT(NSTAGE - 1);
        } else {
            CP_WAIT(0);
        }
        __syncthreads();

        int s = t % NSTAGE;
        const __nv_bfloat16* As_h = (const __nv_bfloat16*)(smem + s*SS);
        const __nv_bfloat16* Bs_h = (const __nv_bfloat16*)(smem + s*SS + A_TB);

        #pragma unroll
        for (int kf = 0; kf < 2; kf++){
            wmma::fragment<wmma::matrix_a, 16, 16, 16, __nv_bfloat16, wmma::row_major> ah[2];
            #pragma unroll
            for (int i = 0; i < 2; i++){
                int r = wr*32 + i*16;
                wmma::load_matrix_sync(ah[i], As_h + r*LDS_E + kf*16, LDS_E);
            }
            #pragma unroll
            for (int j = 0; j < NJ; j++){
                wmma::fragment<wmma::matrix_b, 16, 16, 16, __nv_bfloat16, wmma::col_major> bh;
                int c = wc*WNT + j*16;
                wmma::load_matrix_sync(bh, Bs_h + c*LDS_E + kf*16, LDS_E);
                wmma::mma_sync(acc[0][j], ah[0], bh, acc[0][j]);
                wmma::mma_sync(acc[1][j], ah[1], bh, acc[1][j]);
            }
        }
        __syncthreads();
    }

    if (MODE == 0){
        #pragma unroll
        for (int i = 0; i < 2; i++)
            #pragma unroll
            for (int j = 0; j < NJ; j++){
                float* cp = C + (size_t)(m0 + wr*32 + i*16) * Nc + n0 + wc*WNT + j*16;
                wmma::store_matrix_sync(cp, acc[i][j], Nc, wmma::mem_row_major);
            }
    } else {
        float* stg = (float*)smem + (size_t)wid * (32*STGL);
        #pragma unroll
        for (int i = 0; i < 2; i++)
            #pragma unroll
            for (int j = 0; j < NJ; j++)
                wmma::store_matrix_sync(stg + i*16*STGL + j*16, acc[i][j], STGL,
                                        wmma::mem_row_major);
        __syncwarp();

        int row = m0 + wr*32 + lane;
        int h   = row / 96;
        int w2  = row - h*96;
        bool isx = (w2 < 48);
        int  w   = isx ? w2 : (w2 - 48);
        const float* rsrc = (isx ? rx : ry) + h*48 + w;
        float* od = outp + (isx ? 0 : XFSZ) + h*48 + w;
        #pragma unroll 8
        for (int j = 0; j < WNT; j++){
            int col = n0 + wc*WNT + j;
            od[(size_t)col * PLANE] = stg[lane*STGL + j] + rsrc[(size_t)col * PLANE];
        }
    }
}
// G1: 128x128, 2-stage, 1-term: SS = 20480 -> 40960 B, 2 CTAs/SM
#define GEMM_SMEM_G1 (2 * ((128*LDS_E*2) + (128*LDS_E*2)))
// G2: 64x64, 3-stage, 1-term: SS = 10240 -> 30720 B; staging needs 8*32*36*4 = 36864
#define GEMM_SMEM_G2 36864

// ---------------- 3) causal depthwise conv (K=4) + SiLU, 16 rows/block ----------------
__global__ void conv_silu_kernel(const float* __restrict__ cw){
    int d  = blockIdx.x * 256 + threadIdx.x;  // grid.x = 5
    int l0 = blockIdx.y * 16;                 // grid.y = 288
    float4 wv = ((const float4*)cw)[d];
    const float* xp = g_xz + d;
    float h1 = (l0 >= 1) ? xp[(size_t)(l0-1) * DXZ] : 0.f;
    float h2 = (l0 >= 2) ? xp[(size_t)(l0-2) * DXZ] : 0.f;
    float h3 = (l0 >= 3) ? xp[(size_t)(l0-3) * DXZ] : 0.f;
    #pragma unroll
    for (int i = 0; i < 16; i++){
        float v = xp[(size_t)(l0+i) * DXZ];
        float acc = wv.w*v + wv.z*h1 + wv.y*h2 + wv.x*h3;
        g_xa[(size_t)(l0+i) * DI + d] = silu_f(acc);
        h3 = h2; h2 = h1; h1 = v;
    }
}

// ---------------- 4) proj GEMM split-K=16: xa @ W_xproj ----------------
__global__ void proj_gemm(const float* __restrict__ A, const float* __restrict__ B){
    __shared__ float As[16][64];
    __shared__ float Bs[16][64];
    int tid = threadIdx.x;
    int by  = blockIdx.x;                 // 0..71
    int ks  = blockIdx.y;                 // 0..15
    int k0b = ks * 80;

    int arow = tid >> 2;
    int acol = (tid & 3) * 4;
    const float* Ap = A + (size_t)(by*64 + arow) * DI + k0b + acol;

    float acc[4][4];
    #pragma unroll
    for (int i = 0; i < 4; i++)
        #pragma unroll
        for (int j = 0; j < 4; j++) acc[i][j] = 0.f;

    int ty = tid >> 4, tx = tid & 15;

    for (int k0 = 0; k0 < 80; k0 += 16){
        float4 av = *(const float4*)Ap;
        float bl[4];
        #pragma unroll
        for (int q = 0; q < 4; q++){
            int e = tid*4 + q;
            int rr = e >> 6, c = e & 63;
            bl[q] = (c < NPROJ) ? B[(size_t)(k0b + k0 + rr) * NPROJ + c] : 0.f;
        }
        __syncthreads();
        As[acol+0][arow] = av.x;
        As[acol+1][arow] = av.y;
        As[acol+2][arow] = av.z;
        As[acol+3][arow] = av.w;
        #pragma unroll
        for (int q = 0; q < 4; q++){
            int e = tid*4 + q;
            Bs[e >> 6][e & 63] = bl[q];
        }
        __syncthreads();
        #pragma unroll
        for (int k = 0; k < 16; k++){
            float ar[4], br[4];
            #pragma unroll
            for (int i = 0; i < 4; i++) ar[i] = As[k][ty*4 + i];
            #pragma unroll
            for (int j = 0; j < 4; j++) br[j] = Bs[k][tx*4 + j];
            #pragma unroll
            for (int i = 0; i < 4; i++)
                #pragma unroll
                for (int j = 0; j < 4; j++)
                    acc[i][j] = fmaf(ar[i], br[j], acc[i][j]);
        }
        __syncthreads();
        Ap += 16;
    }
    float* Cp = g_pp + (size_t)ks * PSLICE;
    #pragma unroll
    for (int i = 0; i < 4; i++){
        int row = by*64 + ty*4 + i;
        #pragma unroll
        for (int j = 0; j < 4; j++){
            int col = tx*4 + j;
            if (col < NPROJ) Cp[(size_t)row * NPROJ + col] = acc[i][j];
        }
    }
}

__global__ void proj_reduce(){
    int i = blockIdx.x * 256 + threadIdx.x;
    if (i < PSLICE){
        float a = 0.f;
        #pragma unroll
        for (int k = 0; k < KSPLIT; k++) a += g_pp[(size_t)k * PSLICE + i];
        g_proj[i] = a;
    }
}

// ---------------- 5) dt = softplus(proj[:, :40] @ W_dt + bias), 16 rows/block ------
__global__ void dt_kernel(const float* __restrict__ Wdt, const float* __restrict__ bias){
    __shared__ float pr[16][RANK];
    int t  = threadIdx.x;
    int d  = blockIdx.x * 256 + t;       // grid.x = 5
    int l0 = blockIdx.y * 16;            // grid.y = 288
    for (int e = t; e < 16*RANK; e += 256)
        pr[e / RANK][e % RANK] = g_proj[(size_t)(l0 + e / RANK) * NPROJ + (e % RANK)];
    __syncthreads();

    float acc[16];
    #pragma unroll
    for (int j = 0; j < 16; j++) acc[j] = 0.f;
    for (int k = 0; k < RANK; k++){
        float wv = Wdt[(size_t)k * DI + d];
        #pragma unroll
        for (int j = 0; j < 16; j++) acc[j] = fmaf(pr[j][k], wv, acc[j]);
    }
    float bb = bias[d];
    #pragma unroll
    for (int j = 0; j < 16; j++){
        float v = acc[j] + bb;
        float sp = (v > 20.f) ? v : log1pf(__expf(v));
        g_dt[(size_t)(l0 + j) * DI + d] = sp;
    }
}

// ---------------- 6) chunked parallel scan (72 x 64) ----------------
__global__ void __launch_bounds__(256)
scan_phaseA(const float* __restrict__ A_log){
    int t = threadIdx.x;
    int d = blockIdx.x * 256 + t;
    int g = blockIdx.y;

    float Ac[8];
    #pragma unroll
    for (int s = 0; s < 8; s++) Ac[s] = -__expf(A_log[d*8 + s]);
    bool fast = true;
    #pragma unroll
    for (int s = 0; s < 8; s++){
        float r = Ac[s] / Ac[0];
        if (fabsf(r - (float)(s+1)) > 1e-3f) fast = false;
    }

    float h[8];
    #pragma unroll
    for (int s = 0; s < 8; s++) h[s] = 0.f;
    float Etot = 1.f;

    const float* dtp = g_dt   + (size_t)(g*CLEN) * DI + d;
    const float* xap = g_xa   + (size_t)(g*CLEN) * DI + d;
    const float* bp  = g_proj + (size_t)(g*CLEN) * NPROJ + RANK;

    if (fast){
        for (int l = 0; l < CLEN; l++){
            float dtv = *dtp, xav = *xap;
            float e1 = __expf(dtv * Ac[0]);
            float db = dtv * xav;
            Etot *= e1;
            float p = 1.f;
            #pragma unroll
            for (int s = 0; s < 8; s++){
                p *= e1;
                h[s] = fmaf(p, h[s], db * __ldg(bp + s));
            }
            dtp += DI; xap += DI; bp += NPROJ;
        }
        size_t base = (size_t)g * DS + d*8;
        float P = 1.f;
        #pragma unroll
        for (int s = 0; s < 8; s++){
            P *= Etot;
            g_cP[base + s] = P;
            g_cH[base + s] = h[s];
        }
    } else {
        float Ps[8];
        #pragma unroll
        for (int s = 0; s < 8; s++) Ps[s] = 1.f;
        for (int l = 0; l < CLEN; l++){
            float dtv = *dtp, xav = *xap;
            float db = dtv * xav;
            #pragma unroll
            for (int s = 0; s < 8; s++){
                float dA = __expf(dtv * Ac[s]);
                Ps[s] *= dA;
                h[s] = fmaf(dA, h[s], db * __ldg(bp + s));
            }
            dtp += DI; xap += DI; bp += NPROJ;
        }
        size_t base = (size_t)g * DS + d*8;
        #pragma unroll
        for (int s = 0; s < 8; s++){
            g_cP[base + s] = Ps[s];
            g_cH[base + s] = h[s];
        }
    }
}

__global__ void scan_phaseB(){
    int idx = blockIdx.x * 256 + threadIdx.x;
    float h = 0.f;
    for (int g = 0; g < NCHUNK; g++){
        size_t o = (size_t)g * DS + idx;
        g_h0[o] = h;
        h = fmaf(g_cP[o], h, g_cH[o]);
    }
}

__global__ void __launch_bounds__(256)
scan_phaseC(const float* __restrict__ A_log, const float* __restrict__ Dp){
    int t = threadIdx.x;
    int d = blockIdx.x * 256 + t;
    int g = blockIdx.y;

    float Ac[8];
    #pragma unroll
    for (int s = 0; s < 8; s++) Ac[s] = -__expf(A_log[d*8 + s]);
    bool fast = true;
    #pragma unroll
    for (int s = 0; s < 8; s++){
        float r = Ac[s] / Ac[0];
        if (fabsf(r - (float)(s+1)) > 1e-3f) fast = false;
    }

    float h[8];
    size_t hb = (size_t)g * DS + d*8;
    #pragma unroll
    for (int s = 0; s < 8; s++) h[s] = g_h0[hb + s];
    float Dval = Dp[d];

    const float* dtp = g_dt   + (size_t)(g*CLEN) * DI + d;
    const float* xap = g_xa   + (size_t)(g*CLEN) * DI + d;
    const float* zp  = g_xz   + (size_t)(g*CLEN) * DXZ + DI + d;
    const float* bp  = g_proj + (size_t)(g*CLEN) * NPROJ + RANK;
    size_t yoff = (size_t)(g*CLEN) * DI + d;

    if (fast){
        for (int l = 0; l < CLEN; l++){
            float dtv = *dtp, xav = *xap;
            float e1 = __expf(dtv * Ac[0]);
            float db = dtv * xav;
            float p = 1.f, yv = 0.f;
            #pragma unroll
            for (int s = 0; s < 8; s++){
                p *= e1;
                h[s] = fmaf(p, h[s], db * __ldg(bp + s));
                yv = fmaf(h[s], __ldg(bp + 8 + s), yv);
            }
            float val = (yv + xav * Dval) * silu_f(*zp);
            g_a2hi[yoff] = __float2bfloat16(val);
            dtp += DI; xap += DI; zp += DXZ; bp += NPROJ; yoff += DI;
        }
    } else {
        for (int l = 0; l < CLEN; l++){
            float dtv = *dtp, xav = *xap;
            float db = dtv * xav;
            float yv = 0.f;
            #pragma unroll
            for (int s = 0; s < 8; s++){
                float dA = __expf(dtv * Ac[s]);
                h[s] = fmaf(dA, h[s], db * __ldg(bp + s));
                yv = fmaf(h[s], __ldg(bp + 8 + s), yv);
            }
            float val = (yv + xav * Dval) * silu_f(*zp);
            g_a2hi[yoff] = __float2bfloat16(val);
            dtp += DI; xap += DI; zp += DXZ; bp += NPROJ; yoff += DI;
        }
    }
}

// ---------------- launch ----------------
extern "C" void kernel_launch(void* const* d_in, const int* in_sizes, int n_in,
                              void* d_out, int out_size){
    const float* x       = (const float*)d_in[0];
    const float* y       = (const float*)d_in[1];
    const float* ln_g    = (const float*)d_in[2];
    const float* ln_b    = (const float*)d_in[3];
    const float* W_in    = (const float*)d_in[4];
    const float* conv_w  = (const float*)d_in[5];
    const float* W_xproj = (const float*)d_in[6];
    const float* W_dt    = (const float*)d_in[7];
    const float* dt_bias = (const float*)d_in[8];
    const float* A_log   = (const float*)d_in[9];
    const float* Dp      = (const float*)d_in[10];
    const float* W_out   = (const float*)d_in[11];
    float* out = (float*)d_out;

    cudaFuncSetAttribute((const void*)gemm_wmma<0,4,128,2,2>,
                         cudaFuncAttributeMaxDynamicSharedMemorySize, GEMM_SMEM_G1);
    cudaFuncSetAttribute((const void*)gemm_wmma<1,2,64,3,3>,
                         cudaFuncAttributeMaxDynamicSharedMemorySize, GEMM_SMEM_G2);
    cudaFuncSetAttribute((const void*)ln_kernel,
                         cudaFuncAttributeMaxDynamicSharedMemorySize, LN_SMEM);

    float *xz_p, *xa_p;
    __nv_bfloat16 *a1h, *b1h, *a2h, *b2h;
    cudaGetSymbolAddress((void**)&xz_p, g_xz);
    cudaGetSymbolAddress((void**)&xa_p, g_xa);
    cudaGetSymbolAddress((void**)&a1h, g_a1hi);
    cudaGetSymbolAddress((void**)&b1h, g_b1hi);
    cudaGetSymbolAddress((void**)&a2h, g_a2hi);
    cudaGetSymbolAddress((void**)&b2h, g_b2hi);

    // weight transposes (one launch, bf16)
    transpose_both<<<2400, dim3(32,8)>>>(W_in, W_out, b1h, b2h);

    // 1) gather + layernorm -> a1 (bf16)
    ln_kernel<<<192, 256, LN_SMEM>>>(x, y, ln_g, ln_b);

    // 2) xz = ln(seq) @ W_in   (128x128, 2-stage, 1-term)
    gemm_wmma<0,4,128,2,2><<<dim3(DXZ/128, LSEQ/128), 256, GEMM_SMEM_G1>>>(
        a1h, b1h, xz_p, CDIM, DXZ, nullptr, nullptr, nullptr);

    // 3) xa = silu(causal_dwconv(xp)), 16 rows/block
    conv_silu_kernel<<<dim3(DI/256, LSEQ/16), 256>>>(conv_w);

    // 4) proj = xa @ W_xproj (split-K=16)
    proj_gemm<<<dim3(LSEQ/64, KSPLIT), 256>>>(xa_p, W_xproj);
    proj_reduce<<<(PSLICE + 255)/256, 256>>>();

    // 5) dt (16 rows/block)
    dt_kernel<<<dim3(DI/256, LSEQ/16), 256>>>(W_dt, dt_bias);

    // 6) chunked parallel scan (72 x 64) + gating -> a2 (bf16)
    scan_phaseA<<<dim3(DI/256, NCHUNK), 256>>>(A_log);
    scan_phaseB<<<DS/256, 256>>>();
    scan_phaseC<<<dim3(DI/256, NCHUNK), 256>>>(A_log, Dp);

    // 7) out = yo @ W_out + seq  (64x64, 3-stage, 1-term, fused residual+scatter)
    gemm_wmma<1,2,64,3,3><<<dim3(CDIM/64, LSEQ/64), 256, GEMM_SMEM_G2>>>(
        a2h, b2h, nullptr, DI, CDIM, x, y, out);
}

// round 16
// speedup vs baseline: 1.4925x; 1.0068x over previous
#include <cuda_runtime.h>
#include <cuda_bf16.h>
#include <mma.h>
#include <cstdint>

using namespace nvcuda;

#define LSEQ 4608
#define CDIM 640
#define DI   1280
#define DXZ  2560
#define NPROJ 56
#define RANK  40
#define PLANE 2304          // 48*48
#define XFSZ  (640*2304)
#define PSLICE (LSEQ*NPROJ)
#define NCHUNK 72
#define CLEN   64
#define DS     (DI*8)
#define KSPLIT 16

// ---------------- scratch ----------------
__device__ float g_xz  [LSEQ*DXZ];
__device__ float g_xa  [LSEQ*DI];
__device__ float g_proj[LSEQ*NPROJ];
__device__ float g_pp  [KSPLIT*PSLICE];
__device__ float g_dt  [LSEQ*DI];
__device__ float g_cP  [NCHUNK*DS];
__device__ float g_cH  [NCHUNK*DS];
__device__ float g_h0  [NCHUNK*DS];
// bf16 operands (1-term scheme: bf16 A x bf16 W)
__device__ __align__(256) __nv_bfloat16 g_a1hi[LSEQ*CDIM];   // ln(seq)
__device__ __align__(256) __nv_bfloat16 g_b1hi[DXZ*CDIM];    // W_in^T
__device__ __align__(256) __nv_bfloat16 g_a2hi[LSEQ*DI];     // yo
__device__ __align__(256) __nv_bfloat16 g_b2hi[CDIM*DI];     // W_out^T

// ---------------- helpers ----------------
#define CP_ASYNC16(dst, src) \
    asm volatile("cp.async.cg.shared.global [%0], [%1], 16;" :: "r"(dst), "l"(src) : "memory")
#define CP_COMMIT() asm volatile("cp.async.commit_group;" ::: "memory")
#define CP_WAIT(n)  asm volatile("cp.async.wait_group %0;" :: "n"(n) : "memory")

__device__ __forceinline__ uint32_t smem_u32(const void* p){
    uint32_t a;
    asm("{ .reg .u64 t; cvta.to.shared.u64 t, %1; cvt.u32.u64 %0, t; }" : "=r"(a) : "l"(p));
    return a;
}
__device__ __forceinline__ float silu_f(float v){ return v / (1.0f + __expf(-v)); }

// ---------------- 1) gather + layernorm -> bf16 (coalesced via smem transpose) ----
#define LN_SMEM ((16000 + 640 + 640) * 4)
__global__ void __launch_bounds__(256)
ln_kernel(const float* __restrict__ x, const float* __restrict__ yy,
          const float* __restrict__ g, const float* __restrict__ b){
    extern __shared__ float sm[];             // T[640*25] | gg[640] | bb[640]
    float* T  = sm;
    float* gg = sm + 16000;
    float* bb = sm + 16640;
    int bid = blockIdx.x;                     // 0..191
    bool isx = bid < 96;
    int hb = bid - (isx ? 0 : 96);
    int h  = hb >> 1;
    int w0 = (hb & 1) * 24;
    const float* src = (isx ? x : yy) + h*48 + w0;
    int tid = threadIdx.x;

    for (int e = tid; e < 640; e += 256){ gg[e] = g[e]; bb[e] = b[e]; }
    for (int e = tid; e < 15360; e += 256){
        int c = e / 24, w = e - c*24;
        T[c*25 + w] = src[(size_t)c * PLANE + w];
    }
    __syncthreads();

    int wid = tid >> 5, lane = tid & 31;
    #pragma unroll
    for (int pi = 0; pi < 3; pi++){
        int p = wid + pi*8;                   // 0..23
        float s = 0.f, s2 = 0.f;
        #pragma unroll
        for (int k = 0; k < 20; k++){
            float v = T[(lane + k*32)*25 + p];
            s += v; s2 += v*v;
        }
        #pragma unroll
        for (int o = 16; o; o >>= 1){
            s  += __shfl_xor_sync(0xffffffffu, s , o);
            s2 += __shfl_xor_sync(0xffffffffu, s2, o);
        }
        float mean = s  * (1.f/640.f);
        float var  = s2 * (1.f/640.f) - mean*mean;
        float inv  = rsqrtf(var + 1e-5f);
        int l = h*96 + (isx ? 0 : 48) + w0 + p;
        size_t base = (size_t)l * CDIM;
        #pragma unroll
        for (int k = 0; k < 20; k++){
            int c = lane + k*32;
            float o = (T[c*25 + p] - mean) * inv * gg[c] + bb[c];
            g_a1hi[base + c] = __float2bfloat16(o);
        }
    }
}

// ---------------- weight transposes (both) + bf16 hi: W[K,N] -> Wt[n*K+k] ----------------
__global__ void transpose_both(const float* __restrict__ Wi, const float* __restrict__ Wo,
                               __nv_bfloat16* __restrict__ b1h, __nv_bfloat16* __restrict__ b2h){
    __shared__ float tile[32][33];
    int id = blockIdx.x;
    const float* W; __nv_bfloat16* hi; int K, N, bx, by;
    if (id < 1600){ W = Wi; hi = b1h; K = CDIM; N = DXZ; bx = id % 80; by = id / 80; }
    else { int j = id - 1600; W = Wo; hi = b2h; K = DI; N = CDIM; bx = j % 20; by = j / 20; }
    int n0 = bx * 32, k0 = by * 32;
    int tx = threadIdx.x, ty = threadIdx.y;   // (32, 8)
    #pragma unroll
    for (int i = 0; i < 4; i++)
        tile[ty + 8*i][tx] = W[(size_t)(k0 + ty + 8*i) * N + n0 + tx];
    __syncthreads();
    #pragma unroll
    for (int i = 0; i < 4; i++){
        float v = tile[tx][ty + 8*i];
        hi[(size_t)(n0 + ty + 8*i) * K + k0 + tx] = __float2bfloat16(v);
    }
}

// ---------------- wmma 1-term bf16 GEMM: C = A @ B^T (both bf16, fp32 accum) ---------
#define LDS_E 40                         // bf16 smem row stride (80B)

template<int MODE, int MW, int NTILE, int NSTAGE, int MAXB>
__global__ void __launch_bounds__(256, MAXB)
gemm_wmma(const __nv_bfloat16* __restrict__ A, const __nv_bfloat16* __restrict__ Bhi,
          float* __restrict__ C, int K, int Nc,
          const float* __restrict__ rx, const float* __restrict__ ry,
          float* __restrict__ outp){
    constexpr int MTILE = MW * 32;
    constexpr int NW    = 8 / MW;
    constexpr int WNT   = NTILE / NW;
    constexpr int NJ    = WNT / 16;
    constexpr int A_TB  = MTILE * LDS_E * 2;
    constexpr int B_TB  = NTILE * LDS_E * 2;
    constexpr int SS    = A_TB + B_TB;        // per-stage bytes (A, Bhi)
    constexpr int STGL  = WNT + 4;

    extern __shared__ __align__(32) char smem[];
    uint32_t sbase = smem_u32(smem);
    int tid = threadIdx.x;
    int wid = tid >> 5, lane = tid & 31;
    int wr = wid % MW, wc = wid / MW;
    int n0 = blockIdx.x * NTILE, m0 = blockIdx.y * MTILE;

    const char* asrc = (const char*)(A   + (size_t)m0 * K);
    const char* bsrc = (const char*)(Bhi + (size_t)n0 * K);
    int rowbytes = K * 2;
    int nstage = K / 32;

    wmma::fragment<wmma::accumulator, 16, 16, 16, float> acc[2][NJ];
    #pragma unroll
    for (int i = 0; i < 2; i++)
        #pragma unroll
        for (int j = 0; j < NJ; j++) wmma::fill_fragment(acc[i][j], 0.f);

    auto load_stage = [&](int st, int k0bytes){
        uint32_t sb = sbase + (uint32_t)(st * SS);
        {
            const char* bp = asrc + k0bytes;
            #pragma unroll
            for (int j = 0; j < (MTILE*4)/256; j++){
                int cidx = tid + j*256;
                int row = cidx >> 2, c = cidx & 3;
                CP_ASYNC16(sb + (uint32_t)(row*(LDS_E*2) + c*16),
                           bp + (size_t)row * rowbytes + c*16);
            }
        }
        {
            const char* bp = bsrc + k0bytes;
            uint32_t tb = sb + (uint32_t)A_TB;
            #pragma unroll
            for (int j = 0; j < (NTILE*4)/256; j++){
                int cidx = tid + j*256;
                int row = cidx >> 2, c = cidx & 3;
                CP_ASYNC16(tb + (uint32_t)(row*(LDS_E*2) + c*16),
                           bp + (size_t)row * rowbytes + c*16);
            }
        }
        CP_COMMIT();
    };

    #pragma unroll
    for (int p = 0; p < NSTAGE - 1; p++)
        load_stage(p, p*64);

    for (int t = 0; t < nstage; t++){
        if (t + NSTAGE - 1 < nstage){
            load_stage((t + NSTAGE - 1) % NSTAGE, (t + NSTAGE - 1)*64);
            CP_WAIT(NSTAGE - 1);
        } else {
            CP_WAIT(0);
        }
        __syncthreads();

        int s = t % NSTAGE;
        const __nv_bfloat16* As_h = (const __nv_bfloat16*)(smem + s*SS);
        const __nv_bfloat16* Bs_h = (const __nv_bfloat16*)(smem + s*SS + A_TB);

        #pragma unroll
        for (int kf = 0; kf < 2; kf++){
            wmma::fragment<wmma::matrix_a, 16, 16, 16, __nv_bfloat16, wmma::row_major> ah[2];
            #pragma unroll
            for (int i = 0; i < 2; i++){
                int r = wr*32 + i*16;
                wmma::load_matrix_sync(ah[i], As_h + r*LDS_E + kf*16, LDS_E);
            }
            #pragma unroll
            for (int j = 0; j < NJ; j++){
                wmma::fragment<wmma::matrix_b, 16, 16, 16, __nv_bfloat16, wmma::col_major> bh;
                int c = wc*WNT + j*16;
                wmma::load_matrix_sync(bh, Bs_h + c*LDS_E + kf*16, LDS_E);
                wmma::mma_sync(acc[0][j], ah[0], bh, acc[0][j]);
                wmma::mma_sync(acc[1][j], ah[1], bh, acc[1][j]);
            }
        }
        __syncthreads();
    }

    if (MODE == 0){
        #pragma unroll
        for (int i = 0; i < 2; i++)
            #pragma unroll
            for (int j = 0; j < NJ; j++){
                float* cp = C + (size_t)(m0 + wr*32 + i*16) * Nc + n0 + wc*WNT + j*16;
                wmma::store_matrix_sync(cp, acc[i][j], Nc, wmma::mem_row_major);
            }
    } else {
        float* stg = (float*)smem + (size_t)wid * (32*STGL);
        #pragma unroll
        for (int i = 0; i < 2; i++)
            #pragma unroll
            for (int j = 0; j < NJ; j++)
                wmma::store_matrix_sync(stg + i*16*STGL + j*16, acc[i][j], STGL,
                                        wmma::mem_row_major);
        __syncwarp();

        int row = m0 + wr*32 + lane;
        int h   = row / 96;
        int w2  = row - h*96;
        bool isx = (w2 < 48);
        int  w   = isx ? w2 : (w2 - 48);
        const float* rsrc = (isx ? rx : ry) + h*48 + w;
        float* od = outp + (isx ? 0 : XFSZ) + h*48 + w;
        #pragma unroll 8
        for (int j = 0; j < WNT; j++){
            int col = n0 + wc*WNT + j;
            od[(size_t)col * PLANE] = stg[lane*STGL + j] + rsrc[(size_t)col * PLANE];
        }
    }
}
// G1: 128x128, 2-stage, 1-term: SS = 20480 -> 40960 B, 2 CTAs/SM
#define GEMM_SMEM_G1 (2 * ((128*LDS_E*2) + (128*LDS_E*2)))
// G2: 128x64 (MW=4), 3-stage, 1-term: SS = 10240+5120 = 15360 -> 46080 B, 3 CTAs/SM
#define GEMM_SMEM_G2 (3 * ((128*LDS_E*2) + (64*LDS_E*2)))

// ---------------- 3) causal depthwise conv (K=4) + SiLU, float4 x 16 rows ----------------
__global__ void __launch_bounds__(320)
conv_silu_kernel(const float* __restrict__ cw){
    int d4 = threadIdx.x;                     // 0..319 (block covers all DI/4 groups)
    int l0 = blockIdx.x * 16;                 // grid = 288
    const float4* cw4 = (const float4*)cw;
    float4 w0 = cw4[d4*4+0];
    float4 w1 = cw4[d4*4+1];
    float4 w2 = cw4[d4*4+2];
    float4 w3 = cw4[d4*4+3];
    const float4* xp = (const float4*)g_xz + d4;    // row stride DXZ/4
    float4* xo = (float4*)g_xa + d4;                // row stride DI/4
    float4 zf = {0.f,0.f,0.f,0.f};
    float4 h1 = (l0 >= 1) ? xp[(size_t)(l0-1) * (DXZ/4)] : zf;
    float4 h2 = (l0 >= 2) ? xp[(size_t)(l0-2) * (DXZ/4)] : zf;
    float4 h3 = (l0 >= 3) ? xp[(size_t)(l0-3) * (DXZ/4)] : zf;
    #pragma unroll
    for (int i = 0; i < 16; i++){
        float4 v = xp[(size_t)(l0+i) * (DXZ/4)];
        float4 o;
        o.x = silu_f(w0.w*v.x + w0.z*h1.x + w0.y*h2.x + w0.x*h3.x);
        o.y = silu_f(w1.w*v.y + w1.z*h1.y + w1.y*h2.y + w1.x*h3.y);
        o.z = silu_f(w2.w*v.z + w2.z*h1.z + w2.y*h2.z + w2.x*h3.z);
        o.w = silu_f(w3.w*v.w + w3.z*h1.w + w3.y*h2.w + w3.x*h3.w);
        xo[(size_t)(l0+i) * (DI/4)] = o;
        h3 = h2; h2 = h1; h1 = v;
    }
}

// ---------------- 4) proj GEMM split-K=16: xa @ W_xproj ----------------
__global__ void proj_gemm(const float* __restrict__ A, const float* __restrict__ B){
    __shared__ float As[16][64];
    __shared__ float Bs[16][64];
    int tid = threadIdx.x;
    int by  = blockIdx.x;                 // 0..71
    int ks  = blockIdx.y;                 // 0..15
    int k0b = ks * 80;

    int arow = tid >> 2;
    int acol = (tid & 3) * 4;
    const float* Ap = A + (size_t)(by*64 + arow) * DI + k0b + acol;

    float acc[4][4];
    #pragma unroll
    for (int i = 0; i < 4; i++)
        #pragma unroll
        for (int j = 0; j < 4; j++) acc[i][j] = 0.f;

    int ty = tid >> 4, tx = tid & 15;

    for (int k0 = 0; k0 < 80; k0 += 16){
        float4 av = *(const float4*)Ap;
        float bl[4];
        #pragma unroll
        for (int q = 0; q < 4; q++){
            int e = tid*4 + q;
            int rr = e >> 6, c = e & 63;
            bl[q] = (c < NPROJ) ? B[(size_t)(k0b + k0 + rr) * NPROJ + c] : 0.f;
        }
        __syncthreads();
        As[acol+0][arow] = av.x;
        As[acol+1][arow] = av.y;
        As[acol+2][arow] = av.z;
        As[acol+3][arow] = av.w;
        #pragma unroll
        for (int q = 0; q < 4; q++){
            int e = tid*4 + q;
            Bs[e >> 6][e & 63] = bl[q];
        }
        __syncthreads();
        #pragma unroll
        for (int k = 0; k < 16; k++){
            float ar[4], br[4];
            #pragma unroll
            for (int i = 0; i < 4; i++) ar[i] = As[k][ty*4 + i];
            #pragma unroll
            for (int j = 0; j < 4; j++) br[j] = Bs[k][tx*4 + j];
            #pragma unroll
            for (int i = 0; i < 4; i++)
                #pragma unroll
                for (int j = 0; j < 4; j++)
                    acc[i][j] = fmaf(ar[i], br[j], acc[i][j]);
        }
        __syncthreads();
        Ap += 16;
    }
    float* Cp = g_pp + (size_t)ks * PSLICE;
    #pragma unroll
    for (int i = 0; i < 4; i++){
        int row = by*64 + ty*4 + i;
        #pragma unroll
        for (int j = 0; j < 4; j++){
            int col = tx*4 + j;
            if (col < NPROJ) Cp[(size_t)row * NPROJ + col] = acc[i][j];
        }
    }
}

__global__ void proj_reduce(){
    int i = blockIdx.x * 256 + threadIdx.x;
    if (i < PSLICE){
        float a = 0.f;
        #pragma unroll
        for (int k = 0; k < KSPLIT; k++) a += g_pp[(size_t)k * PSLICE + i];
        g_proj[i] = a;
    }
}

// ---------------- 5) dt = softplus(proj[:, :40] @ W_dt + bias), 16 rows/block ------
__global__ void dt_kernel(const float* __restrict__ Wdt, const float* __restrict__ bias){
    __shared__ float pr[16][RANK];
    int t  = threadIdx.x;
    int d  = blockIdx.x * 256 + t;       // grid.x = 5
    int l0 = blockIdx.y * 16;            // grid.y = 288
    for (int e = t; e < 16*RANK; e += 256)
        pr[e / RANK][e % RANK] = g_proj[(size_t)(l0 + e / RANK) * NPROJ + (e % RANK)];
    __syncthreads();

    float acc[16];
    #pragma unroll
    for (int j = 0; j < 16; j++) acc[j] = 0.f;
    for (int k = 0; k < RANK; k++){
        float wv = Wdt[(size_t)k * DI + d];
        #pragma unroll
        for (int j = 0; j < 16; j++) acc[j] = fmaf(pr[j][k], wv, acc[j]);
    }
    float bb = bias[d];
    #pragma unroll
    for (int j = 0; j < 16; j++){
        float v = acc[j] + bb;
        float sp = (v > 20.f) ? v : log1pf(__expf(v));
        g_dt[(size_t)(l0 + j) * DI + d] = sp;
    }
}

// ---------------- 6) chunked parallel scan (72 x 64) ----------------
__global__ void __launch_bounds__(256)
scan_phaseA(const float* __restrict__ A_log){
    int t = threadIdx.x;
    int d = blockIdx.x * 256 + t;
    int g = blockIdx.y;

    float Ac[8];
    #pragma unroll
    for (int s = 0; s < 8; s++) Ac[s] = -__expf(A_log[d*8 + s]);
    bool fast = true;
    #pragma unroll
    for (int s = 0; s < 8; s++){
        float r = Ac[s] / Ac[0];
        if (fabsf(r - (float)(s+1)) > 1e-3f) fast = false;
    }

    float h[8];
    #pragma unroll
    for (int s = 0; s < 8; s++) h[s] = 0.f;
    float Etot = 1.f;

    const float* dtp = g_dt   + (size_t)(g*CLEN) * DI + d;
    const float* xap = g_xa   + (size_t)(g*CLEN) * DI + d;
    const float* bp  = g_proj + (size_t)(g*CLEN) * NPROJ + RANK;

    if (fast){
        for (int l = 0; l < CLEN; l++){
            float dtv = *dtp, xav = *xap;
            float e1 = __expf(dtv * Ac[0]);
            float db = dtv * xav;
            Etot *= e1;
            float p = 1.f;
            #pragma unroll
            for (int s = 0; s < 8; s++){
                p *= e1;
                h[s] = fmaf(p, h[s], db * __ldg(bp + s));
            }
            dtp += DI; xap += DI; bp += NPROJ;
        }
        size_t base = (size_t)g * DS + d*8;
        float P = 1.f;
        #pragma unroll
        for (int s = 0; s < 8; s++){
            P *= Etot;
            g_cP[base + s] = P;
            g_cH[base + s] = h[s];
        }
    } else {
        float Ps[8];
        #pragma unroll
        for (int s = 0; s < 8; s++) Ps[s] = 1.f;
        for (int l = 0; l < CLEN; l++){
            float dtv = *dtp, xav = *xap;
            float db = dtv * xav;
            #pragma unroll
            for (int s = 0; s < 8; s++){
                float dA = __expf(dtv * Ac[s]);
                Ps[s] *= dA;
                h[s] = fmaf(dA, h[s], db * __ldg(bp + s));
            }
            dtp += DI; xap += DI; bp += NPROJ;
        }
        size_t base = (size_t)g * DS + d*8;
        #pragma unroll
        for (int s = 0; s < 8; s++){
            g_cP[base + s] = Ps[s];
            g_cH[base + s] = h[s];
        }
    }
}

__global__ void scan_phaseB(){
    int idx = blockIdx.x * 256 + threadIdx.x;
    float h = 0.f;
    for (int g = 0; g < NCHUNK; g++){
        size_t o = (size_t)g * DS + idx;
        g_h0[o] = h;
        h = fmaf(g_cP[o], h, g_cH[o]);
    }
}

__global__ void __launch_bounds__(256)
scan_phaseC(const float* __restrict__ A_log, const float* __restrict__ Dp){
    int t = threadIdx.x;
    int d = blockIdx.x * 256 + t;
    int g = blockIdx.y;

    float Ac[8];
    #pragma unroll
    for (int s = 0; s < 8; s++) Ac[s] = -__expf(A_log[d*8 + s]);
    bool fast = true;
    #pragma unroll
    for (int s = 0; s < 8; s++){
        float r = Ac[s] / Ac[0];
        if (fabsf(r - (float)(s+1)) > 1e-3f) fast = false;
    }

    float h[8];
    size_t hb = (size_t)g * DS + d*8;
    #pragma unroll
    for (int s = 0; s < 8; s++) h[s] = g_h0[hb + s];
    float Dval = Dp[d];

    const float* dtp = g_dt   + (size_t)(g*CLEN) * DI + d;
    const float* xap = g_xa   + (size_t)(g*CLEN) * DI + d;
    const float* zp  = g_xz   + (size_t)(g*CLEN) * DXZ + DI + d;
    const float* bp  = g_proj + (size_t)(g*CLEN) * NPROJ + RANK;
    size_t yoff = (size_t)(g*CLEN) * DI + d;

    if (fast){
        for (int l = 0; l < CLEN; l++){
            float dtv = *dtp, xav = *xap;
            float e1 = __expf(dtv * Ac[0]);
            float db = dtv * xav;
            float p = 1.f, yv = 0.f;
            #pragma unroll
            for (int s = 0; s < 8; s++){
                p *= e1;
                h[s] = fmaf(p, h[s], db * __ldg(bp + s));
                yv = fmaf(h[s], __ldg(bp + 8 + s), yv);
            }
            float val = (yv + xav * Dval) * silu_f(*zp);
            g_a2hi[yoff] = __float2bfloat16(val);
            dtp += DI; xap += DI; zp += DXZ; bp += NPROJ; yoff += DI;
        }
    } else {
        for (int l = 0; l < CLEN; l++){
            float dtv = *dtp, xav = *xap;
            float db = dtv * xav;
            float yv = 0.f;
            #pragma unroll
            for (int s = 0; s < 8; s++){
                float dA = __expf(dtv * Ac[s]);
                h[s] = fmaf(dA, h[s], db * __ldg(bp + s));
                yv = fmaf(h[s], __ldg(bp + 8 + s), yv);
            }
            float val = (yv + xav * Dval) * silu_f(*zp);
            g_a2hi[yoff] = __float2bfloat16(val);
            dtp += DI; xap += DI; zp += DXZ; bp += NPROJ; yoff += DI;
        }
    }
}

// ---------------- launch ----------------
extern "C" void kernel_launch(void* const* d_in, const int* in_sizes, int n_in,
                              void* d_out, int out_size){
    const float* x       = (const float*)d_in[0];
    const float* y       = (const float*)d_in[1];
    const float* ln_g    = (const float*)d_in[2];
    const float* ln_b    = (const float*)d_in[3];
    const float* W_in    = (const float*)d_in[4];
    const float* conv_w  = (const float*)d_in[5];
    const float* W_xproj = (const float*)d_in[6];
    const float* W_dt    = (const float*)d_in[7];
    const float* dt_bias = (const float*)d_in[8];
    const float* A_log   = (const float*)d_in[9];
    const float* Dp      = (const float*)d_in[10];
    const float* W_out   = (const float*)d_in[11];
    float* out = (float*)d_out;

    cudaFuncSetAttribute((const void*)gemm_wmma<0,4,128,2,2>,
                         cudaFuncAttributeMaxDynamicSharedMemorySize, GEMM_SMEM_G1);
    cudaFuncSetAttribute((const void*)gemm_wmma<1,4,64,3,3>,
                         cudaFuncAttributeMaxDynamicSharedMemorySize, GEMM_SMEM_G2);
    cudaFuncSetAttribute((const void*)ln_kernel,
                         cudaFuncAttributeMaxDynamicSharedMemorySize, LN_SMEM);

    float *xz_p, *xa_p;
    __nv_bfloat16 *a1h, *b1h, *a2h, *b2h;
    cudaGetSymbolAddress((void**)&xz_p, g_xz);
    cudaGetSymbolAddress((void**)&xa_p, g_xa);
    cudaGetSymbolAddress((void**)&a1h, g_a1hi);
    cudaGetSymbolAddress((void**)&b1h, g_b1hi);
    cudaGetSymbolAddress((void**)&a2h, g_a2hi);
    cudaGetSymbolAddress((void**)&b2h, g_b2hi);

    // weight transposes (one launch, bf16)
    transpose_both<<<2400, dim3(32,8)>>>(W_in, W_out, b1h, b2h);

    // 1) gather + layernorm -> a1 (bf16)
    ln_kernel<<<192, 256, LN_SMEM>>>(x, y, ln_g, ln_b);

    // 2) xz = ln(seq) @ W_in   (128x128, 2-stage, 1-term)
    gemm_wmma<0,4,128,2,2><<<dim3(DXZ/128, LSEQ/128), 256, GEMM_SMEM_G1>>>(
        a1h, b1h, xz_p, CDIM, DXZ, nullptr, nullptr, nullptr);

    // 3) xa = silu(causal_dwconv(xp)), float4 x 16 rows
    conv_silu_kernel<<<LSEQ/16, 320>>>(conv_w);

    // 4) proj = xa @ W_xproj (split-K=16)
    proj_gemm<<<dim3(LSEQ/64, KSPLIT), 256>>>(xa_p, W_xproj);
    proj_reduce<<<(PSLICE + 255)/256, 256>>>();

    // 5) dt (16 rows/block)
    dt_kernel<<<dim3(DI/256, LSEQ/16), 256>>>(W_dt, dt_bias);

    // 6) chunked parallel scan (72 x 64) + gating -> a2 (bf16)
    scan_phaseA<<<dim3(DI/256, NCHUNK), 256>>>(A_log);
    scan_phaseB<<<DS/256, 256>>>();
    scan_phaseC<<<dim3(DI/256, NCHUNK), 256>>>(A_log, Dp);

    // 7) out = yo @ W_out + seq  (128x64 MW=4, 3-stage, 1-term, single wave)
    gemm_wmma<1,4,64,3,3><<<dim3(CDIM/64, LSEQ/128), 256, GEMM_SMEM_G2>>>(
        a2h, b2h, nullptr, DI, CDIM, x, y, out);
}